// round 1
// baseline (speedup 1.0000x reference)
#include <cuda_runtime.h>
#include <math.h>

#define T_TOK 8192
#define EMB   1024
#define DFF   4096
#define NH    16
#define DH    64
#define SEQ   2048
#define NBATCH 4

// ---------------- scratch (no allocation allowed) ----------------
__device__ float g_xn[(size_t)T_TOK * EMB];
__device__ float g_q [(size_t)T_TOK * EMB];
__device__ float g_k [(size_t)T_TOK * EMB];
__device__ float g_v [(size_t)T_TOK * EMB];
__device__ float g_at[(size_t)T_TOK * EMB];
__device__ float g_x1[(size_t)T_TOK * EMB];
__device__ float g_h [(size_t)T_TOK * DFF];

// ---------------- LayerNorm: one block per token row ----------------
__global__ void layernorm_kernel(const float* __restrict__ x,
                                 const float* __restrict__ gamma,
                                 const float* __restrict__ beta,
                                 float* __restrict__ out) {
    int row = blockIdx.x;
    int t = threadIdx.x;                      // 256 threads, 4 floats each
    const float4* xr = (const float4*)(x + (size_t)row * EMB);
    float4 v = xr[t];
    float s  = v.x + v.y + v.z + v.w;
    float ss = v.x*v.x + v.y*v.y + v.z*v.z + v.w*v.w;
    #pragma unroll
    for (int o = 16; o > 0; o >>= 1) {
        s  += __shfl_xor_sync(0xffffffffu, s,  o);
        ss += __shfl_xor_sync(0xffffffffu, ss, o);
    }
    __shared__ float rs[8], rss[8];
    if ((t & 31) == 0) { rs[t >> 5] = s; rss[t >> 5] = ss; }
    __syncthreads();
    float sum = 0.f, sumsq = 0.f;
    #pragma unroll
    for (int i = 0; i < 8; i++) { sum += rs[i]; sumsq += rss[i]; }
    float mu  = sum * (1.0f / EMB);
    float var = sumsq * (1.0f / EMB) - mu * mu;
    float inv = rsqrtf(var + 1e-5f);
    float4 gg = ((const float4*)gamma)[t];
    float4 bb = ((const float4*)beta)[t];
    float4 o;
    o.x = (v.x - mu) * inv * gg.x + bb.x;
    o.y = (v.y - mu) * inv * gg.y + bb.y;
    o.z = (v.z - mu) * inv * gg.z + bb.z;
    o.w = (v.w - mu) * inv * gg.w + bb.w;
    ((float4*)(out + (size_t)row * EMB))[t] = o;
}

// ---------------- GEMM: C[M,N] = A[M,K] @ B[N,K]^T (+bias,+relu,+residual) ----
// 128x128 tile, BK=8, 256 threads, 8x8 per-thread microtile.
template <bool BIAS, bool RELU, bool RES>
__global__ __launch_bounds__(256)
void gemm_kernel(const float* __restrict__ A, const float* __restrict__ B,
                 const float* __restrict__ bias, const float* __restrict__ res,
                 float* __restrict__ C, int M, int N, int K) {
    const int BM = 128, BN = 128, BK = 8;
    __shared__ float As[BK][BM];
    __shared__ float Bs[BK][BN];

    int bm = blockIdx.y * BM;
    int bn = blockIdx.x * BN;
    int tid = threadIdx.x;

    int lrow = tid >> 1;          // 0..127
    int lcol = (tid & 1) << 2;    // 0 or 4

    int tx = tid & 15;            // column group
    int ty = tid >> 4;            // row group

    float acc[8][8];
    #pragma unroll
    for (int i = 0; i < 8; i++)
        #pragma unroll
        for (int j = 0; j < 8; j++) acc[i][j] = 0.f;

    const float* Ap = A + (size_t)(bm + lrow) * K + lcol;
    const float* Bp = B + (size_t)(bn + lrow) * K + lcol;

    for (int k0 = 0; k0 < K; k0 += BK) {
        float4 av = *(const float4*)(Ap + k0);
        float4 bv = *(const float4*)(Bp + k0);
        As[lcol + 0][lrow] = av.x; As[lcol + 1][lrow] = av.y;
        As[lcol + 2][lrow] = av.z; As[lcol + 3][lrow] = av.w;
        Bs[lcol + 0][lrow] = bv.x; Bs[lcol + 1][lrow] = bv.y;
        Bs[lcol + 2][lrow] = bv.z; Bs[lcol + 3][lrow] = bv.w;
        __syncthreads();
        #pragma unroll
        for (int k = 0; k < BK; k++) {
            float ar[8], br[8];
            #pragma unroll
            for (int i = 0; i < 8; i++) ar[i] = As[k][ty * 8 + i];
            #pragma unroll
            for (int j = 0; j < 8; j++) br[j] = Bs[k][tx * 8 + j];
            #pragma unroll
            for (int i = 0; i < 8; i++)
                #pragma unroll
                for (int j = 0; j < 8; j++)
                    acc[i][j] = fmaf(ar[i], br[j], acc[i][j]);
        }
        __syncthreads();
    }

    #pragma unroll
    for (int i = 0; i < 8; i++) {
        int m = bm + ty * 8 + i;
        #pragma unroll
        for (int j = 0; j < 8; j += 4) {
            int n = bn + tx * 8 + j;
            float4 c;
            c.x = acc[i][j + 0]; c.y = acc[i][j + 1];
            c.z = acc[i][j + 2]; c.w = acc[i][j + 3];
            if (BIAS) {
                float4 bb = *(const float4*)(bias + n);
                c.x += bb.x; c.y += bb.y; c.z += bb.z; c.w += bb.w;
            }
            if (RELU) {
                c.x = fmaxf(c.x, 0.f); c.y = fmaxf(c.y, 0.f);
                c.z = fmaxf(c.z, 0.f); c.w = fmaxf(c.w, 0.f);
            }
            if (RES) {
                float4 rr = *(const float4*)(res + (size_t)m * N + n);
                c.x += rr.x; c.y += rr.y; c.z += rr.z; c.w += rr.w;
            }
            *(float4*)(C + (size_t)m * N + n) = c;
        }
    }
}

// ---------------- Flash attention (fp32), 1 q row per thread --------------
// grid: (SEQ/128, NBATCH*NH), 128 threads.
__global__ __launch_bounds__(128)
void attention_kernel(const float* __restrict__ Q, const float* __restrict__ K,
                      const float* __restrict__ V, float* __restrict__ O) {
    __shared__ float Ksh[64][64];
    __shared__ float Vsh[64][64];

    int bh = blockIdx.y;
    int b = bh / NH, h = bh % NH;
    int q0 = blockIdx.x * 128;
    int tid = threadIdx.x;

    const size_t base = ((size_t)b * SEQ) * EMB + (size_t)h * DH;
    const float* Qp = Q + base + (size_t)(q0 + tid) * EMB;
    const float* Kp = K + base;
    const float* Vp = V + base;

    float qreg[DH];
    #pragma unroll
    for (int d = 0; d < DH; d++) qreg[d] = Qp[d] * 0.125f;  // 1/sqrt(64)

    float acc[DH];
    #pragma unroll
    for (int d = 0; d < DH; d++) acc[d] = 0.f;
    float mrun = -1e30f, lrun = 0.f;

    for (int k0 = 0; k0 < SEQ; k0 += 64) {
        // cooperative coalesced load of 64x64 K and V tiles
        #pragma unroll
        for (int i = 0; i < 8; i++) {
            int f = tid + i * 128;         // 0..1023 float4 slots
            int r = f >> 4;
            int c = (f & 15) << 2;
            *(float4*)&Ksh[r][c] = *(const float4*)(Kp + (size_t)(k0 + r) * EMB + c);
            *(float4*)&Vsh[r][c] = *(const float4*)(Vp + (size_t)(k0 + r) * EMB + c);
        }
        __syncthreads();

        float s[64];
        float tmax = -1e30f;
        #pragma unroll 4
        for (int j = 0; j < 64; j++) {
            const float4* kr = (const float4*)Ksh[j];
            float a = 0.f;
            #pragma unroll
            for (int d4 = 0; d4 < 16; d4++) {
                float4 t = kr[d4];
                a = fmaf(qreg[4*d4+0], t.x, a);
                a = fmaf(qreg[4*d4+1], t.y, a);
                a = fmaf(qreg[4*d4+2], t.z, a);
                a = fmaf(qreg[4*d4+3], t.w, a);
            }
            s[j] = a;
            tmax = fmaxf(tmax, a);
        }

        float mnew = fmaxf(mrun, tmax);
        float corr = __expf(mrun - mnew);
        lrun *= corr;
        #pragma unroll
        for (int d = 0; d < DH; d++) acc[d] *= corr;

        #pragma unroll 2
        for (int j = 0; j < 64; j++) {
            float p = __expf(s[j] - mnew);
            lrun += p;
            const float4* vr = (const float4*)Vsh[j];
            #pragma unroll
            for (int d4 = 0; d4 < 16; d4++) {
                float4 t = vr[d4];
                acc[4*d4+0] = fmaf(p, t.x, acc[4*d4+0]);
                acc[4*d4+1] = fmaf(p, t.y, acc[4*d4+1]);
                acc[4*d4+2] = fmaf(p, t.z, acc[4*d4+2]);
                acc[4*d4+3] = fmaf(p, t.w, acc[4*d4+3]);
            }
        }
        mrun = mnew;
        __syncthreads();
    }

    float invl = 1.0f / lrun;
    float* Op = O + base + (size_t)(q0 + tid) * EMB;
    #pragma unroll
    for (int d = 0; d < DH; d++) Op[d] = acc[d] * invl;
}

// ---------------- launcher ----------------
extern "C" void kernel_launch(void* const* d_in, const int* in_sizes, int n_in,
                              void* d_out, int out_size) {
    const float* x     = (const float*)d_in[0];
    const float* Wq    = (const float*)d_in[1];
    const float* Wk    = (const float*)d_in[2];
    const float* Wv    = (const float*)d_in[3];
    const float* Wo    = (const float*)d_in[4];
    const float* bo    = (const float*)d_in[5];
    const float* ln1g  = (const float*)d_in[6];
    const float* ln1b  = (const float*)d_in[7];
    const float* ln2g  = (const float*)d_in[8];
    const float* ln2b  = (const float*)d_in[9];
    const float* W1    = (const float*)d_in[10];
    const float* b1    = (const float*)d_in[11];
    const float* W2    = (const float*)d_in[12];
    const float* b2    = (const float*)d_in[13];
    float* out = (float*)d_out;

    float *xn, *q, *k, *v, *at, *x1, *h;
    cudaGetSymbolAddress((void**)&xn, g_xn);
    cudaGetSymbolAddress((void**)&q,  g_q);
    cudaGetSymbolAddress((void**)&k,  g_k);
    cudaGetSymbolAddress((void**)&v,  g_v);
    cudaGetSymbolAddress((void**)&at, g_at);
    cudaGetSymbolAddress((void**)&x1, g_x1);
    cudaGetSymbolAddress((void**)&h,  g_h);

    // 1. LN1
    layernorm_kernel<<<T_TOK, 256>>>(x, ln1g, ln1b, xn);

    // 2. Q/K/V projections
    dim3 gE(EMB / 128, T_TOK / 128);
    gemm_kernel<false, false, false><<<gE, 256>>>(xn, Wq, nullptr, nullptr, q,  T_TOK, EMB, EMB);
    gemm_kernel<false, false, false><<<gE, 256>>>(xn, Wk, nullptr, nullptr, k,  T_TOK, EMB, EMB);
    gemm_kernel<false, false, false><<<gE, 256>>>(xn, Wv, nullptr, nullptr, v,  T_TOK, EMB, EMB);

    // 3. attention
    attention_kernel<<<dim3(SEQ / 128, NBATCH * NH), 128>>>(q, k, v, at);

    // 4. O projection + bias + residual(x)
    gemm_kernel<true, false, true><<<gE, 256>>>(at, Wo, bo, x, x1, T_TOK, EMB, EMB);

    // 5. LN2
    layernorm_kernel<<<T_TOK, 256>>>(x1, ln2g, ln2b, xn);

    // 6. FF1 + bias + relu
    dim3 gF(DFF / 128, T_TOK / 128);
    gemm_kernel<true, true, false><<<gF, 256>>>(xn, W1, b1, nullptr, h, T_TOK, DFF, EMB);

    // 7. FF2 + bias + residual(x1) -> out
    gemm_kernel<true, false, true><<<gE, 256>>>(h, W2, b2, x1, out, T_TOK, EMB, DFF);
}

// round 3
// speedup vs baseline: 1.7436x; 1.7436x over previous
#include <cuda_runtime.h>
#include <cuda_bf16.h>
#include <math.h>
#include <cstdint>

#define T_TOK 8192
#define EMB   1024
#define DFF   4096
#define NH    16
#define DH    64
#define SEQ   2048
#define NBATCH 4

// ================= PTX helpers (portable sm_80+ subset) =================
__device__ __forceinline__ uint32_t smem_u32(const void* p) {
    uint32_t a;
    asm("{ .reg .u64 t; cvta.to.shared.u64 t, %1; cvt.u32.u64 %0, t; }" : "=r"(a) : "l"(p));
    return a;
}
#define CP_ASYNC16(dst, src) \
    asm volatile("cp.async.cg.shared.global [%0], [%1], 16;" :: "r"(dst), "l"(src))
#define CP_COMMIT() asm volatile("cp.async.commit_group;" ::: "memory")
#define CP_WAIT1()  asm volatile("cp.async.wait_group 1;" ::: "memory")
#define CP_WAIT0()  asm volatile("cp.async.wait_group 0;" ::: "memory")

__device__ __forceinline__ void ldsm4(uint32_t* r, uint32_t addr) {
    asm volatile("ldmatrix.sync.aligned.m8n8.x4.shared.b16 {%0,%1,%2,%3}, [%4];"
                 : "=r"(r[0]), "=r"(r[1]), "=r"(r[2]), "=r"(r[3]) : "r"(addr));
}
__device__ __forceinline__ void mma_bf16(float* c, const uint32_t* a, const uint32_t* b) {
    asm volatile(
        "mma.sync.aligned.m16n8k16.row.col.f32.bf16.bf16.f32 "
        "{%0,%1,%2,%3}, {%4,%5,%6,%7}, {%8,%9}, {%0,%1,%2,%3};"
        : "+f"(c[0]), "+f"(c[1]), "+f"(c[2]), "+f"(c[3])
        : "r"(a[0]), "r"(a[1]), "r"(a[2]), "r"(a[3]), "r"(b[0]), "r"(b[1]));
}

// ================= scratch =================
__device__ __nv_bfloat16 g_xnh[(size_t)T_TOK * EMB];
__device__ __nv_bfloat16 g_xnl[(size_t)T_TOK * EMB];
__device__ float g_q [(size_t)T_TOK * EMB];
__device__ float g_k [(size_t)T_TOK * EMB];
__device__ float g_v [(size_t)T_TOK * EMB];
__device__ float g_x1[(size_t)T_TOK * EMB];
__device__ __nv_bfloat16 g_ath[(size_t)T_TOK * EMB];
__device__ __nv_bfloat16 g_atl[(size_t)T_TOK * EMB];
__device__ __nv_bfloat16 g_hh[(size_t)T_TOK * DFF];
__device__ __nv_bfloat16 g_hl[(size_t)T_TOK * DFF];
__device__ __nv_bfloat16 g_wqh[(size_t)EMB * EMB], g_wql[(size_t)EMB * EMB];
__device__ __nv_bfloat16 g_wkh[(size_t)EMB * EMB], g_wkl[(size_t)EMB * EMB];
__device__ __nv_bfloat16 g_wvh[(size_t)EMB * EMB], g_wvl[(size_t)EMB * EMB];
__device__ __nv_bfloat16 g_woh[(size_t)EMB * EMB], g_wol[(size_t)EMB * EMB];
__device__ __nv_bfloat16 g_w1h[(size_t)DFF * EMB], g_w1l[(size_t)DFF * EMB];
__device__ __nv_bfloat16 g_w2h[(size_t)EMB * DFF], g_w2l[(size_t)EMB * DFF];

__device__ __forceinline__ void split_bf16(float x, __nv_bfloat16& h, __nv_bfloat16& l) {
    h = __float2bfloat16(x);
    l = __float2bfloat16(x - __bfloat162float(h));
}

// ================= weight fp32 -> (hi,lo) bf16 =================
__global__ void cvt_pair_kernel(const float* __restrict__ w,
                                __nv_bfloat16* __restrict__ hi,
                                __nv_bfloat16* __restrict__ lo, int n4) {
    int i = blockIdx.x * blockDim.x + threadIdx.x;
    if (i >= n4) return;
    float4 v = ((const float4*)w)[i];
    __nv_bfloat16 h0, l0, h1, l1, h2, l2, h3, l3;
    split_bf16(v.x, h0, l0); split_bf16(v.y, h1, l1);
    split_bf16(v.z, h2, l2); split_bf16(v.w, h3, l3);
    __nv_bfloat162 hh0; hh0.x = h0; hh0.y = h1;
    __nv_bfloat162 hh1; hh1.x = h2; hh1.y = h3;
    __nv_bfloat162 ll0; ll0.x = l0; ll0.y = l1;
    __nv_bfloat162 ll1; ll1.x = l2; ll1.y = l3;
    ((__nv_bfloat162*)hi)[i * 2 + 0] = hh0;
    ((__nv_bfloat162*)hi)[i * 2 + 1] = hh1;
    ((__nv_bfloat162*)lo)[i * 2 + 0] = ll0;
    ((__nv_bfloat162*)lo)[i * 2 + 1] = ll1;
}

// ================= LayerNorm -> (hi,lo) bf16 =================
__global__ void layernorm_kernel(const float* __restrict__ x,
                                 const float* __restrict__ gamma,
                                 const float* __restrict__ beta,
                                 __nv_bfloat16* __restrict__ oh,
                                 __nv_bfloat16* __restrict__ ol) {
    int row = blockIdx.x;
    int t = threadIdx.x;
    const float4* xr = (const float4*)(x + (size_t)row * EMB);
    float4 v = xr[t];
    float s  = v.x + v.y + v.z + v.w;
    float ss = v.x * v.x + v.y * v.y + v.z * v.z + v.w * v.w;
    #pragma unroll
    for (int o = 16; o > 0; o >>= 1) {
        s  += __shfl_xor_sync(0xffffffffu, s,  o);
        ss += __shfl_xor_sync(0xffffffffu, ss, o);
    }
    __shared__ float rs[8], rss[8];
    if ((t & 31) == 0) { rs[t >> 5] = s; rss[t >> 5] = ss; }
    __syncthreads();
    float sum = 0.f, sumsq = 0.f;
    #pragma unroll
    for (int i = 0; i < 8; i++) { sum += rs[i]; sumsq += rss[i]; }
    float mu  = sum * (1.0f / EMB);
    float var = sumsq * (1.0f / EMB) - mu * mu;
    float inv = rsqrtf(var + 1e-5f);
    float4 gg = ((const float4*)gamma)[t];
    float4 bb = ((const float4*)beta)[t];
    float y0 = (v.x - mu) * inv * gg.x + bb.x;
    float y1 = (v.y - mu) * inv * gg.y + bb.y;
    float y2 = (v.z - mu) * inv * gg.z + bb.z;
    float y3 = (v.w - mu) * inv * gg.w + bb.w;
    __nv_bfloat16 h0, l0, h1, l1, h2, l2, h3, l3;
    split_bf16(y0, h0, l0); split_bf16(y1, h1, l1);
    split_bf16(y2, h2, l2); split_bf16(y3, h3, l3);
    size_t base2 = (size_t)row * (EMB / 2) + t * 2;
    __nv_bfloat162 hh0; hh0.x = h0; hh0.y = h1;
    __nv_bfloat162 hh1; hh1.x = h2; hh1.y = h3;
    __nv_bfloat162 ll0; ll0.x = l0; ll0.y = l1;
    __nv_bfloat162 ll1; ll1.x = l2; ll1.y = l3;
    ((__nv_bfloat162*)oh)[base2 + 0] = hh0;
    ((__nv_bfloat162*)oh)[base2 + 1] = hh1;
    ((__nv_bfloat162*)ol)[base2 + 0] = ll0;
    ((__nv_bfloat162*)ol)[base2 + 1] = ll1;
}

// ================= split-bf16 GEMM via mma.sync =================
// C[M,N] = A[M,K] @ B[N,K]^T ; A,B as (hi,lo) bf16 pairs; fp32 accum.
// 128x128 CTA tile, BK=32, 8 warps (2Mx4N), warp tile 64x32.
// SMEM stage: 4 tiles (Ah,Al,Bh,Bl), each 128 rows x 64B data + 16B pad (80B stride).
#define ROWB     80
#define TILE_B   (128 * ROWB)            // 10240
#define STAGE_B  (4 * TILE_B)            // 40960
#define GEMM_SMEM (2 * STAGE_B)          // 81920

template <int OM, bool BIAS, bool RELU, bool RES>   // OM: 0=f32 out, 1=bf16-pair out
__global__ __launch_bounds__(256, 1)
void tc_gemm_kernel(const __nv_bfloat16* __restrict__ Ah, const __nv_bfloat16* __restrict__ Al,
                    const __nv_bfloat16* __restrict__ Bh, const __nv_bfloat16* __restrict__ Bl,
                    const float* __restrict__ bias, const float* __restrict__ res,
                    float* __restrict__ Cf,
                    __nv_bfloat16* __restrict__ Ch, __nv_bfloat16* __restrict__ Cl,
                    int M, int N, int K) {
    extern __shared__ char smc[];
    const uint32_t smb = smem_u32(smc);
    const int tid  = threadIdx.x;
    const int wid  = tid >> 5;
    const int lane = tid & 31;
    const int wm   = wid & 1;     // 0..1  (64-row halves)
    const int wn   = wid >> 1;    // 0..3  (32-col quarters)
    const int bm   = blockIdx.y * 128;
    const int bn   = blockIdx.x * 128;

    // ---- cp.async source/dest precompute: thread covers chunks {tid, tid+256} per tile
    // chunk c: row = c>>2 (0..127), col = c&3 (16B units within 64B row)
    const int r0 = tid >> 2,  c0 = (tid & 3);
    const int r1 = (tid + 256) >> 2, c1 = ((tid + 256) & 3);

    // ---- ldmatrix address lanes
    // A: m_local = lane&15, k byte off = (lane>>4)*16
    const uint32_t a_off = (uint32_t)((wm * 64 + (lane & 15)) * ROWB + (lane >> 4) * 16);
    // B: n_local = ((lane>>4)&1)*8 + (lane&7), k byte off = ((lane>>3)&1)*16
    const uint32_t b_off = (uint32_t)((wn * 32 + ((lane >> 4) & 1) * 8 + (lane & 7)) * ROWB
                                      + ((lane >> 3) & 1) * 16);

    float acc[4][4][4];
    #pragma unroll
    for (int i = 0; i < 4; i++)
        #pragma unroll
        for (int j = 0; j < 4; j++)
            #pragma unroll
            for (int q = 0; q < 4; q++) acc[i][j][q] = 0.f;

    const int S = K >> 5;   // stages of BK=32

    // issue one stage of cp.async into buffer buf
    auto issue = [&](int s, int buf) {
        int k0 = s << 5;
        uint32_t dstb = smb + buf * STAGE_B;
        {
            uint32_t d = dstb + r0 * ROWB + c0 * 16;
            size_t ao = (size_t)(bm + r0) * K + k0 + c0 * 8;
            size_t bo = (size_t)(bn + r0) * K + k0 + c0 * 8;
            CP_ASYNC16(d,              Ah + ao);
            CP_ASYNC16(d + TILE_B,     Al + ao);
            CP_ASYNC16(d + 2 * TILE_B, Bh + bo);
            CP_ASYNC16(d + 3 * TILE_B, Bl + bo);
        }
        {
            uint32_t d = dstb + r1 * ROWB + c1 * 16;
            size_t ao = (size_t)(bm + r1) * K + k0 + c1 * 8;
            size_t bo = (size_t)(bn + r1) * K + k0 + c1 * 8;
            CP_ASYNC16(d,              Ah + ao);
            CP_ASYNC16(d + TILE_B,     Al + ao);
            CP_ASYNC16(d + 2 * TILE_B, Bh + bo);
            CP_ASYNC16(d + 3 * TILE_B, Bl + bo);
        }
    };

    issue(0, 0); CP_COMMIT();
    if (S > 1) { issue(1, 1); CP_COMMIT(); }
    CP_WAIT1();
    __syncthreads();

    for (int s = 0; s < S; s++) {
        const uint32_t stg = smb + (s & 1) * STAGE_B;
        const uint32_t aB = stg + a_off;
        const uint32_t bB = stg + 2 * TILE_B + b_off;
        #pragma unroll
        for (int ks = 0; ks < 2; ks++) {
            const uint32_t ko = ks * 32;   // 16 bf16 = 32B per kstep
            uint32_t ahf[4][4], alf[4][4];
            #pragma unroll
            for (int mt = 0; mt < 4; mt++) {
                ldsm4(ahf[mt], aB + mt * (16 * ROWB) + ko);
                ldsm4(alf[mt], aB + TILE_B + mt * (16 * ROWB) + ko);
            }
            uint32_t bhf[2][4], blf[2][4];
            #pragma unroll
            for (int p = 0; p < 2; p++) {
                ldsm4(bhf[p], bB + p * (16 * ROWB) + ko);
                ldsm4(blf[p], bB + TILE_B + p * (16 * ROWB) + ko);
            }
            #pragma unroll
            for (int mt = 0; mt < 4; mt++) {
                #pragma unroll
                for (int nt = 0; nt < 4; nt++) {
                    const uint32_t* bh = &bhf[nt >> 1][(nt & 1) * 2];
                    const uint32_t* bl = &blf[nt >> 1][(nt & 1) * 2];
                    mma_bf16(acc[mt][nt], ahf[mt], bh);
                    mma_bf16(acc[mt][nt], ahf[mt], bl);
                    mma_bf16(acc[mt][nt], alf[mt], bh);
                }
            }
        }
        __syncthreads();
        if (s + 1 < S) {
            if (s + 2 < S) { issue(s + 2, s & 1); CP_COMMIT(); CP_WAIT1(); }
            else           { CP_WAIT0(); }
            __syncthreads();
        }
    }

    // ---- epilogue: fragment (m = t/4 [+8], n = (t%4)*2 [,+1])
    const int me = bm + wm * 64 + (lane >> 2);
    const int ne = bn + wn * 32 + (lane & 3) * 2;
    #pragma unroll
    for (int mt = 0; mt < 4; mt++) {
        #pragma unroll
        for (int nt = 0; nt < 4; nt++) {
            #pragma unroll
            for (int half = 0; half < 2; half++) {
                int m = me + mt * 16 + half * 8;
                int n = ne + nt * 8;
                float v0 = acc[mt][nt][half * 2 + 0];
                float v1 = acc[mt][nt][half * 2 + 1];
                if (BIAS) {
                    float2 bb = *(const float2*)(bias + n);
                    v0 += bb.x; v1 += bb.y;
                }
                if (RELU) { v0 = fmaxf(v0, 0.f); v1 = fmaxf(v1, 0.f); }
                if (RES) {
                    float2 rr = *(const float2*)(res + (size_t)m * N + n);
                    v0 += rr.x; v1 += rr.y;
                }
                if (OM == 0) {
                    float2 o; o.x = v0; o.y = v1;
                    *(float2*)(Cf + (size_t)m * N + n) = o;
                } else {
                    __nv_bfloat16 h0, l0, h1, l1;
                    split_bf16(v0, h0, l0); split_bf16(v1, h1, l1);
                    __nv_bfloat162 hh; hh.x = h0; hh.y = h1;
                    __nv_bfloat162 ll; ll.x = l0; ll.y = l1;
                    *(__nv_bfloat162*)(Ch + (size_t)m * N + n) = hh;
                    *(__nv_bfloat162*)(Cl + (size_t)m * N + n) = ll;
                }
            }
        }
    }
}

// ================= Flash attention (fp32 SIMT) -> bf16-pair out =============
__global__ __launch_bounds__(128)
void attention_kernel(const float* __restrict__ Q, const float* __restrict__ K,
                      const float* __restrict__ V,
                      __nv_bfloat16* __restrict__ Oh, __nv_bfloat16* __restrict__ Ol) {
    __shared__ float Ksh[64][64];
    __shared__ float Vsh[64][64];

    int bh = blockIdx.y;
    int b = bh / NH, h = bh % NH;
    int q0 = blockIdx.x * 128;
    int tid = threadIdx.x;

    const size_t base = ((size_t)b * SEQ) * EMB + (size_t)h * DH;
    const float* Qp = Q + base + (size_t)(q0 + tid) * EMB;
    const float* Kp = K + base;
    const float* Vp = V + base;

    float qreg[DH];
    #pragma unroll
    for (int d = 0; d < DH; d++) qreg[d] = Qp[d] * 0.125f;

    float acc[DH];
    #pragma unroll
    for (int d = 0; d < DH; d++) acc[d] = 0.f;
    float mrun = -1e30f, lrun = 0.f;

    for (int k0 = 0; k0 < SEQ; k0 += 64) {
        #pragma unroll
        for (int i = 0; i < 8; i++) {
            int f = tid + i * 128;
            int rr = f >> 4;
            int cc = (f & 15) << 2;
            *(float4*)&Ksh[rr][cc] = *(const float4*)(Kp + (size_t)(k0 + rr) * EMB + cc);
            *(float4*)&Vsh[rr][cc] = *(const float4*)(Vp + (size_t)(k0 + rr) * EMB + cc);
        }
        __syncthreads();

        float s[64];
        float tmax = -1e30f;
        #pragma unroll 4
        for (int j = 0; j < 64; j++) {
            const float4* kr = (const float4*)Ksh[j];
            float a = 0.f;
            #pragma unroll
            for (int d4 = 0; d4 < 16; d4++) {
                float4 t = kr[d4];
                a = fmaf(qreg[4 * d4 + 0], t.x, a);
                a = fmaf(qreg[4 * d4 + 1], t.y, a);
                a = fmaf(qreg[4 * d4 + 2], t.z, a);
                a = fmaf(qreg[4 * d4 + 3], t.w, a);
            }
            s[j] = a;
            tmax = fmaxf(tmax, a);
        }

        float mnew = fmaxf(mrun, tmax);
        float corr = __expf(mrun - mnew);
        lrun *= corr;
        #pragma unroll
        for (int d = 0; d < DH; d++) acc[d] *= corr;

        #pragma unroll 2
        for (int j = 0; j < 64; j++) {
            float p = __expf(s[j] - mnew);
            lrun += p;
            const float4* vr = (const float4*)Vsh[j];
            #pragma unroll
            for (int d4 = 0; d4 < 16; d4++) {
                float4 t = vr[d4];
                acc[4 * d4 + 0] = fmaf(p, t.x, acc[4 * d4 + 0]);
                acc[4 * d4 + 1] = fmaf(p, t.y, acc[4 * d4 + 1]);
                acc[4 * d4 + 2] = fmaf(p, t.z, acc[4 * d4 + 2]);
                acc[4 * d4 + 3] = fmaf(p, t.w, acc[4 * d4 + 3]);
            }
        }
        mrun = mnew;
        __syncthreads();
    }

    float invl = 1.0f / lrun;
    size_t obase = base + (size_t)(q0 + tid) * EMB;
    #pragma unroll
    for (int d = 0; d < DH; d += 2) {
        float o0 = acc[d] * invl, o1 = acc[d + 1] * invl;
        __nv_bfloat16 h0, l0, h1, l1;
        split_bf16(o0, h0, l0); split_bf16(o1, h1, l1);
        __nv_bfloat162 hh; hh.x = h0; hh.y = h1;
        __nv_bfloat162 ll; ll.x = l0; ll.y = l1;
        *(__nv_bfloat162*)(Oh + obase + d) = hh;
        *(__nv_bfloat162*)(Ol + obase + d) = ll;
    }
}

// ================= launcher =================
extern "C" void kernel_launch(void* const* d_in, const int* in_sizes, int n_in,
                              void* d_out, int out_size) {
    const float* x    = (const float*)d_in[0];
    const float* Wq   = (const float*)d_in[1];
    const float* Wk   = (const float*)d_in[2];
    const float* Wv   = (const float*)d_in[3];
    const float* Wo   = (const float*)d_in[4];
    const float* bo   = (const float*)d_in[5];
    const float* ln1g = (const float*)d_in[6];
    const float* ln1b = (const float*)d_in[7];
    const float* ln2g = (const float*)d_in[8];
    const float* ln2b = (const float*)d_in[9];
    const float* W1   = (const float*)d_in[10];
    const float* b1   = (const float*)d_in[11];
    const float* W2   = (const float*)d_in[12];
    const float* b2   = (const float*)d_in[13];
    float* out = (float*)d_out;

    __nv_bfloat16 *xnh, *xnl, *ath, *atl, *hh, *hl;
    __nv_bfloat16 *wqh, *wql, *wkh, *wkl, *wvh, *wvl, *woh, *wol, *w1h, *w1l, *w2h, *w2l;
    float *q, *k, *v, *x1;
    cudaGetSymbolAddress((void**)&xnh, g_xnh); cudaGetSymbolAddress((void**)&xnl, g_xnl);
    cudaGetSymbolAddress((void**)&ath, g_ath); cudaGetSymbolAddress((void**)&atl, g_atl);
    cudaGetSymbolAddress((void**)&hh,  g_hh);  cudaGetSymbolAddress((void**)&hl,  g_hl);
    cudaGetSymbolAddress((void**)&wqh, g_wqh); cudaGetSymbolAddress((void**)&wql, g_wql);
    cudaGetSymbolAddress((void**)&wkh, g_wkh); cudaGetSymbolAddress((void**)&wkl, g_wkl);
    cudaGetSymbolAddress((void**)&wvh, g_wvh); cudaGetSymbolAddress((void**)&wvl, g_wvl);
    cudaGetSymbolAddress((void**)&woh, g_woh); cudaGetSymbolAddress((void**)&wol, g_wol);
    cudaGetSymbolAddress((void**)&w1h, g_w1h); cudaGetSymbolAddress((void**)&w1l, g_w1l);
    cudaGetSymbolAddress((void**)&w2h, g_w2h); cudaGetSymbolAddress((void**)&w2l, g_w2l);
    cudaGetSymbolAddress((void**)&q,  g_q);  cudaGetSymbolAddress((void**)&k,  g_k);
    cudaGetSymbolAddress((void**)&v,  g_v);  cudaGetSymbolAddress((void**)&x1, g_x1);

    cudaFuncSetAttribute(tc_gemm_kernel<0, false, false, false>,
                         cudaFuncAttributeMaxDynamicSharedMemorySize, GEMM_SMEM);
    cudaFuncSetAttribute(tc_gemm_kernel<0, true, false, true>,
                         cudaFuncAttributeMaxDynamicSharedMemorySize, GEMM_SMEM);
    cudaFuncSetAttribute(tc_gemm_kernel<1, true, true, false>,
                         cudaFuncAttributeMaxDynamicSharedMemorySize, GEMM_SMEM);

    // weight conversion
    const int CT = 256;
    int nE = EMB * EMB / 4, nF = DFF * EMB / 4;
    cvt_pair_kernel<<<nE / CT, CT>>>(Wq, wqh, wql, nE);
    cvt_pair_kernel<<<nE / CT, CT>>>(Wk, wkh, wkl, nE);
    cvt_pair_kernel<<<nE / CT, CT>>>(Wv, wvh, wvl, nE);
    cvt_pair_kernel<<<nE / CT, CT>>>(Wo, woh, wol, nE);
    cvt_pair_kernel<<<nF / CT, CT>>>(W1, w1h, w1l, nF);
    cvt_pair_kernel<<<nF / CT, CT>>>(W2, w2h, w2l, nF);

    // 1. LN1 -> xn pair
    layernorm_kernel<<<T_TOK, 256>>>(x, ln1g, ln1b, xnh, xnl);

    // 2. QKV projections
    dim3 gE(EMB / 128, T_TOK / 128);
    tc_gemm_kernel<0, false, false, false><<<gE, 256, GEMM_SMEM>>>(
        xnh, xnl, wqh, wql, nullptr, nullptr, q, nullptr, nullptr, T_TOK, EMB, EMB);
    tc_gemm_kernel<0, false, false, false><<<gE, 256, GEMM_SMEM>>>(
        xnh, xnl, wkh, wkl, nullptr, nullptr, k, nullptr, nullptr, T_TOK, EMB, EMB);
    tc_gemm_kernel<0, false, false, false><<<gE, 256, GEMM_SMEM>>>(
        xnh, xnl, wvh, wvl, nullptr, nullptr, v, nullptr, nullptr, T_TOK, EMB, EMB);

    // 3. attention -> at pair
    attention_kernel<<<dim3(SEQ / 128, NBATCH * NH), 128>>>(q, k, v, ath, atl);

    // 4. O projection + bias + residual(x) -> x1 (f32)
    tc_gemm_kernel<0, true, false, true><<<gE, 256, GEMM_SMEM>>>(
        ath, atl, woh, wol, bo, x, x1, nullptr, nullptr, T_TOK, EMB, EMB);

    // 5. LN2 -> xn pair
    layernorm_kernel<<<T_TOK, 256>>>(x1, ln2g, ln2b, xnh, xnl);

    // 6. FF1 + bias + relu -> h pair
    dim3 gF(DFF / 128, T_TOK / 128);
    tc_gemm_kernel<1, true, true, false><<<gF, 256, GEMM_SMEM>>>(
        xnh, xnl, w1h, w1l, b1, nullptr, nullptr, hh, hl, T_TOK, DFF, EMB);

    // 7. FF2 + bias + residual(x1) -> out (f32)
    tc_gemm_kernel<0, true, false, true><<<gE, 256, GEMM_SMEM>>>(
        hh, hl, w2h, w2l, b2, x1, out, nullptr, nullptr, T_TOK, EMB, DFF);
}

// round 4
// speedup vs baseline: 3.0216x; 1.7330x over previous
#include <cuda_runtime.h>
#include <cuda_bf16.h>
#include <math.h>
#include <cstdint>

#define T_TOK 8192
#define EMB   1024
#define DFF   4096
#define NH    16
#define DH    64
#define SEQ   2048
#define NBATCH 4

// ================= PTX helpers (portable sm_80+ subset) =================
__device__ __forceinline__ uint32_t smem_u32(const void* p) {
    uint32_t a;
    asm("{ .reg .u64 t; cvta.to.shared.u64 t, %1; cvt.u32.u64 %0, t; }" : "=r"(a) : "l"(p));
    return a;
}
#define CP_ASYNC16(dst, src) \
    asm volatile("cp.async.cg.shared.global [%0], [%1], 16;" :: "r"(dst), "l"(src))
#define CP_COMMIT() asm volatile("cp.async.commit_group;" ::: "memory")
#define CP_WAIT1()  asm volatile("cp.async.wait_group 1;" ::: "memory")
#define CP_WAIT0()  asm volatile("cp.async.wait_group 0;" ::: "memory")

__device__ __forceinline__ void ldsm4(uint32_t* r, uint32_t addr) {
    asm volatile("ldmatrix.sync.aligned.m8n8.x4.shared.b16 {%0,%1,%2,%3}, [%4];"
                 : "=r"(r[0]), "=r"(r[1]), "=r"(r[2]), "=r"(r[3]) : "r"(addr));
}
__device__ __forceinline__ void mma_bf16(float* c, const uint32_t* a, const uint32_t* b) {
    asm volatile(
        "mma.sync.aligned.m16n8k16.row.col.f32.bf16.bf16.f32 "
        "{%0,%1,%2,%3}, {%4,%5,%6,%7}, {%8,%9}, {%0,%1,%2,%3};"
        : "+f"(c[0]), "+f"(c[1]), "+f"(c[2]), "+f"(c[3])
        : "r"(a[0]), "r"(a[1]), "r"(a[2]), "r"(a[3]), "r"(b[0]), "r"(b[1]));
}
__device__ __forceinline__ float ex2(float x) {
    float y;
    asm("ex2.approx.f32 %0, %1;" : "=f"(y) : "f"(x));
    return y;
}

// ================= scratch =================
__device__ __nv_bfloat16 g_xnh[(size_t)T_TOK * EMB];
__device__ __nv_bfloat16 g_xnl[(size_t)T_TOK * EMB];
__device__ float g_q [(size_t)T_TOK * EMB];
__device__ float g_k [(size_t)T_TOK * EMB];
__device__ float g_v [(size_t)T_TOK * EMB];
__device__ float g_x1[(size_t)T_TOK * EMB];
__device__ __nv_bfloat16 g_ath[(size_t)T_TOK * EMB];
__device__ __nv_bfloat16 g_atl[(size_t)T_TOK * EMB];
__device__ __nv_bfloat16 g_hh[(size_t)T_TOK * DFF];
__device__ __nv_bfloat16 g_hl[(size_t)T_TOK * DFF];
__device__ __nv_bfloat16 g_wqh[(size_t)EMB * EMB], g_wql[(size_t)EMB * EMB];
__device__ __nv_bfloat16 g_wkh[(size_t)EMB * EMB], g_wkl[(size_t)EMB * EMB];
__device__ __nv_bfloat16 g_wvh[(size_t)EMB * EMB], g_wvl[(size_t)EMB * EMB];
__device__ __nv_bfloat16 g_woh[(size_t)EMB * EMB], g_wol[(size_t)EMB * EMB];
__device__ __nv_bfloat16 g_w1h[(size_t)DFF * EMB], g_w1l[(size_t)DFF * EMB];
__device__ __nv_bfloat16 g_w2h[(size_t)EMB * DFF], g_w2l[(size_t)EMB * DFF];

__device__ __forceinline__ void split_bf16(float x, __nv_bfloat16& h, __nv_bfloat16& l) {
    h = __float2bfloat16(x);
    l = __float2bfloat16(x - __bfloat162float(h));
}
__device__ __forceinline__ void split2_u32(float a, float b, uint32_t& hi, uint32_t& lo) {
    __nv_bfloat16 ha, la, hb, lb;
    split_bf16(a, ha, la); split_bf16(b, hb, lb);
    __nv_bfloat162 h2; h2.x = ha; h2.y = hb;
    __nv_bfloat162 l2; l2.x = la; l2.y = lb;
    hi = *(uint32_t*)&h2; lo = *(uint32_t*)&l2;
}

// ================= weight fp32 -> (hi,lo) bf16 =================
__global__ void cvt_pair_kernel(const float* __restrict__ w,
                                __nv_bfloat16* __restrict__ hi,
                                __nv_bfloat16* __restrict__ lo, int n4) {
    int i = blockIdx.x * blockDim.x + threadIdx.x;
    if (i >= n4) return;
    float4 v = ((const float4*)w)[i];
    uint32_t h0, l0, h1, l1;
    split2_u32(v.x, v.y, h0, l0);
    split2_u32(v.z, v.w, h1, l1);
    ((uint32_t*)hi)[i * 2 + 0] = h0;
    ((uint32_t*)hi)[i * 2 + 1] = h1;
    ((uint32_t*)lo)[i * 2 + 0] = l0;
    ((uint32_t*)lo)[i * 2 + 1] = l1;
}

// ================= LayerNorm -> (hi,lo) bf16 =================
__global__ void layernorm_kernel(const float* __restrict__ x,
                                 const float* __restrict__ gamma,
                                 const float* __restrict__ beta,
                                 __nv_bfloat16* __restrict__ oh,
                                 __nv_bfloat16* __restrict__ ol) {
    int row = blockIdx.x;
    int t = threadIdx.x;
    const float4* xr = (const float4*)(x + (size_t)row * EMB);
    float4 v = xr[t];
    float s  = v.x + v.y + v.z + v.w;
    float ss = v.x * v.x + v.y * v.y + v.z * v.z + v.w * v.w;
    #pragma unroll
    for (int o = 16; o > 0; o >>= 1) {
        s  += __shfl_xor_sync(0xffffffffu, s,  o);
        ss += __shfl_xor_sync(0xffffffffu, ss, o);
    }
    __shared__ float rs[8], rss[8];
    if ((t & 31) == 0) { rs[t >> 5] = s; rss[t >> 5] = ss; }
    __syncthreads();
    float sum = 0.f, sumsq = 0.f;
    #pragma unroll
    for (int i = 0; i < 8; i++) { sum += rs[i]; sumsq += rss[i]; }
    float mu  = sum * (1.0f / EMB);
    float var = sumsq * (1.0f / EMB) - mu * mu;
    float inv = rsqrtf(var + 1e-5f);
    float4 gg = ((const float4*)gamma)[t];
    float4 bb = ((const float4*)beta)[t];
    float y0 = (v.x - mu) * inv * gg.x + bb.x;
    float y1 = (v.y - mu) * inv * gg.y + bb.y;
    float y2 = (v.z - mu) * inv * gg.z + bb.z;
    float y3 = (v.w - mu) * inv * gg.w + bb.w;
    uint32_t h0, l0, h1, l1;
    split2_u32(y0, y1, h0, l0);
    split2_u32(y2, y3, h1, l1);
    size_t base2 = (size_t)row * (EMB / 2) + t * 2;
    ((uint32_t*)oh)[base2 + 0] = h0;
    ((uint32_t*)oh)[base2 + 1] = h1;
    ((uint32_t*)ol)[base2 + 0] = l0;
    ((uint32_t*)ol)[base2 + 1] = l1;
}

// ================= split-bf16 GEMM via mma.sync (unchanged, validated) ======
#define ROWB     80
#define TILE_B   (128 * ROWB)
#define STAGE_B  (4 * TILE_B)
#define GEMM_SMEM (2 * STAGE_B)

template <int OM, bool BIAS, bool RELU, bool RES>
__global__ __launch_bounds__(256, 1)
void tc_gemm_kernel(const __nv_bfloat16* __restrict__ Ah, const __nv_bfloat16* __restrict__ Al,
                    const __nv_bfloat16* __restrict__ Bh, const __nv_bfloat16* __restrict__ Bl,
                    const float* __restrict__ bias, const float* __restrict__ res,
                    float* __restrict__ Cf,
                    __nv_bfloat16* __restrict__ Ch, __nv_bfloat16* __restrict__ Cl,
                    int M, int N, int K) {
    extern __shared__ char smc[];
    const uint32_t smb = smem_u32(smc);
    const int tid  = threadIdx.x;
    const int wid  = tid >> 5;
    const int lane = tid & 31;
    const int wm   = wid & 1;
    const int wn   = wid >> 1;
    const int bm   = blockIdx.y * 128;
    const int bn   = blockIdx.x * 128;

    const int r0 = tid >> 2,  c0 = (tid & 3);
    const int r1 = (tid + 256) >> 2, c1 = ((tid + 256) & 3);

    const uint32_t a_off = (uint32_t)((wm * 64 + (lane & 15)) * ROWB + (lane >> 4) * 16);
    const uint32_t b_off = (uint32_t)((wn * 32 + ((lane >> 4) & 1) * 8 + (lane & 7)) * ROWB
                                      + ((lane >> 3) & 1) * 16);

    float acc[4][4][4];
    #pragma unroll
    for (int i = 0; i < 4; i++)
        #pragma unroll
        for (int j = 0; j < 4; j++)
            #pragma unroll
            for (int q = 0; q < 4; q++) acc[i][j][q] = 0.f;

    const int S = K >> 5;

    auto issue = [&](int s, int buf) {
        int k0 = s << 5;
        uint32_t dstb = smb + buf * STAGE_B;
        {
            uint32_t d = dstb + r0 * ROWB + c0 * 16;
            size_t ao = (size_t)(bm + r0) * K + k0 + c0 * 8;
            size_t bo = (size_t)(bn + r0) * K + k0 + c0 * 8;
            CP_ASYNC16(d,              Ah + ao);
            CP_ASYNC16(d + TILE_B,     Al + ao);
            CP_ASYNC16(d + 2 * TILE_B, Bh + bo);
            CP_ASYNC16(d + 3 * TILE_B, Bl + bo);
        }
        {
            uint32_t d = dstb + r1 * ROWB + c1 * 16;
            size_t ao = (size_t)(bm + r1) * K + k0 + c1 * 8;
            size_t bo = (size_t)(bn + r1) * K + k0 + c1 * 8;
            CP_ASYNC16(d,              Ah + ao);
            CP_ASYNC16(d + TILE_B,     Al + ao);
            CP_ASYNC16(d + 2 * TILE_B, Bh + bo);
            CP_ASYNC16(d + 3 * TILE_B, Bl + bo);
        }
    };

    issue(0, 0); CP_COMMIT();
    if (S > 1) { issue(1, 1); CP_COMMIT(); }
    CP_WAIT1();
    __syncthreads();

    for (int s = 0; s < S; s++) {
        const uint32_t stg = smb + (s & 1) * STAGE_B;
        const uint32_t aB = stg + a_off;
        const uint32_t bB = stg + 2 * TILE_B + b_off;
        #pragma unroll
        for (int ks = 0; ks < 2; ks++) {
            const uint32_t ko = ks * 32;
            uint32_t ahf[4][4], alf[4][4];
            #pragma unroll
            for (int mt = 0; mt < 4; mt++) {
                ldsm4(ahf[mt], aB + mt * (16 * ROWB) + ko);
                ldsm4(alf[mt], aB + TILE_B + mt * (16 * ROWB) + ko);
            }
            uint32_t bhf[2][4], blf[2][4];
            #pragma unroll
            for (int p = 0; p < 2; p++) {
                ldsm4(bhf[p], bB + p * (16 * ROWB) + ko);
                ldsm4(blf[p], bB + TILE_B + p * (16 * ROWB) + ko);
            }
            #pragma unroll
            for (int mt = 0; mt < 4; mt++) {
                #pragma unroll
                for (int nt = 0; nt < 4; nt++) {
                    const uint32_t* bh = &bhf[nt >> 1][(nt & 1) * 2];
                    const uint32_t* bl = &blf[nt >> 1][(nt & 1) * 2];
                    mma_bf16(acc[mt][nt], ahf[mt], bh);
                    mma_bf16(acc[mt][nt], ahf[mt], bl);
                    mma_bf16(acc[mt][nt], alf[mt], bh);
                }
            }
        }
        __syncthreads();
        if (s + 1 < S) {
            if (s + 2 < S) { issue(s + 2, s & 1); CP_COMMIT(); CP_WAIT1(); }
            else           { CP_WAIT0(); }
            __syncthreads();
        }
    }

    const int me = bm + wm * 64 + (lane >> 2);
    const int ne = bn + wn * 32 + (lane & 3) * 2;
    #pragma unroll
    for (int mt = 0; mt < 4; mt++) {
        #pragma unroll
        for (int nt = 0; nt < 4; nt++) {
            #pragma unroll
            for (int half = 0; half < 2; half++) {
                int m = me + mt * 16 + half * 8;
                int n = ne + nt * 8;
                float v0 = acc[mt][nt][half * 2 + 0];
                float v1 = acc[mt][nt][half * 2 + 1];
                if (BIAS) {
                    float2 bb = *(const float2*)(bias + n);
                    v0 += bb.x; v1 += bb.y;
                }
                if (RELU) { v0 = fmaxf(v0, 0.f); v1 = fmaxf(v1, 0.f); }
                if (RES) {
                    float2 rr = *(const float2*)(res + (size_t)m * N + n);
                    v0 += rr.x; v1 += rr.y;
                }
                if (OM == 0) {
                    float2 o; o.x = v0; o.y = v1;
                    *(float2*)(Cf + (size_t)m * N + n) = o;
                } else {
                    uint32_t hi, lo;
                    split2_u32(v0, v1, hi, lo);
                    *(uint32_t*)(Ch + (size_t)m * N + n) = hi;
                    *(uint32_t*)(Cl + (size_t)m * N + n) = lo;
                }
            }
        }
    }
}

// ================= tensor-core flash attention (split-bf16) =================
// grid (SEQ/128, NB*NH), 256 threads (8 warps, m16 each). kv tile = 64.
// SMEM byte offsets (row stride 144B = 72 halves):
#define AT_ROWB 144
#define OQH 0
#define OQL 18432
#define OKH 36864
#define OKL 46080
#define OVH 55296
#define OVL 64512
#define ATT_SMEM 73728
#define QSCALE 0.18033688f   /* 0.125 * log2(e) */

__global__ __launch_bounds__(256, 1)
void attention_tc_kernel(const float* __restrict__ Q, const float* __restrict__ K,
                         const float* __restrict__ V,
                         __nv_bfloat16* __restrict__ Oh, __nv_bfloat16* __restrict__ Ol) {
    extern __shared__ char smc[];
    const uint32_t smb = smem_u32(smc);
    const int tid  = threadIdx.x;
    const int wid  = tid >> 5;
    const int lane = tid & 31;
    const int bh = blockIdx.y;
    const int b = bh >> 4, h = bh & 15;
    const int q0 = blockIdx.x * 128;
    const size_t base = ((size_t)b * SEQ) * EMB + (size_t)h * DH;

    // ---- load Q tile (128x64 f32), scale, split -> SMEM
    {
        int row = tid >> 1;
        int cf  = (tid & 1) * 32;               // float offset in row
        const float4* qp = (const float4*)(Q + base + (size_t)(q0 + row) * EMB + cf);
        uint32_t dst = smb + row * AT_ROWB + cf * 2;
        #pragma unroll
        for (int i = 0; i < 8; i++) {
            float4 v = qp[i];
            uint32_t h0, l0, h1, l1;
            split2_u32(v.x * QSCALE, v.y * QSCALE, h0, l0);
            split2_u32(v.z * QSCALE, v.w * QSCALE, h1, l1);
            *(uint32_t*)(smc + (dst - smb) + OQH + i * 8)     = h0;
            *(uint32_t*)(smc + (dst - smb) + OQH + i * 8 + 4) = h1;
            *(uint32_t*)(smc + (dst - smb) + OQL + i * 8)     = l0;
            *(uint32_t*)(smc + (dst - smb) + OQL + i * 8 + 4) = l1;
        }
    }
    __syncthreads();

    // ---- per-warp Q A-fragments (kept in regs for whole kernel)
    uint32_t qh[4][4], ql[4][4];
    {
        uint32_t a_off = (uint32_t)((wid * 16 + (lane & 15)) * AT_ROWB + (lane >> 4) * 16);
        #pragma unroll
        for (int ks = 0; ks < 4; ks++) {
            ldsm4(qh[ks], smb + OQH + a_off + ks * 32);
            ldsm4(ql[ks], smb + OQL + a_off + ks * 32);
        }
    }

    float oacc[8][4];
    #pragma unroll
    for (int i = 0; i < 8; i++)
        #pragma unroll
        for (int j = 0; j < 4; j++) oacc[i][j] = 0.f;
    float m0 = -1e30f, m1 = -1e30f, l0 = 0.f, l1 = 0.f;

    // K/V tile loading: thread covers kv row tid>>2, 16 d-cols (tid&3)*16
    const int kvr = tid >> 2;
    const int cd  = (tid & 3) * 16;
    const float* Kp = K + base + (size_t)kvr * EMB + cd;
    const float* Vp = V + base + (size_t)kvr * EMB + cd;

    float4 kreg[4], vreg[4];
    #pragma unroll
    for (int i = 0; i < 4; i++) {
        kreg[i] = ((const float4*)Kp)[i];
        vreg[i] = ((const float4*)Vp)[i];
    }

    const uint32_t b_off = (uint32_t)((((lane >> 4) & 1) * 8 + (lane & 7)) * AT_ROWB
                                      + ((lane >> 3) & 1) * 16);

    for (int t = 0; t < SEQ / 64; t++) {
        // ---- store K (split) and V (split + transpose) to SMEM
        {
            uint32_t kd = smb + kvr * AT_ROWB + cd * 2;
            #pragma unroll
            for (int i = 0; i < 4; i++) {
                uint32_t h0, l0u, h1, l1u;
                split2_u32(kreg[i].x, kreg[i].y, h0, l0u);
                split2_u32(kreg[i].z, kreg[i].w, h1, l1u);
                *(uint32_t*)(smc + (kd - smb) + OKH + i * 8)     = h0;
                *(uint32_t*)(smc + (kd - smb) + OKH + i * 8 + 4) = h1;
                *(uint32_t*)(smc + (kd - smb) + OKL + i * 8)     = l0u;
                *(uint32_t*)(smc + (kd - smb) + OKL + i * 8 + 4) = l1u;
            }
            __nv_bfloat16* vth = (__nv_bfloat16*)(smc + OVH);
            __nv_bfloat16* vtl = (__nv_bfloat16*)(smc + OVL);
            #pragma unroll
            for (int i = 0; i < 4; i++) {
                float vv[4] = {vreg[i].x, vreg[i].y, vreg[i].z, vreg[i].w};
                #pragma unroll
                for (int j = 0; j < 4; j++) {
                    int d = cd + i * 4 + j;
                    __nv_bfloat16 hb, lb;
                    split_bf16(vv[j], hb, lb);
                    vth[d * 72 + kvr] = hb;
                    vtl[d * 72 + kvr] = lb;
                }
            }
        }
        __syncthreads();

        // ---- prefetch next tile
        if (t + 1 < SEQ / 64) {
            const float* Kn = Kp + (size_t)(t + 1) * 64 * EMB;
            const float* Vn = Vp + (size_t)(t + 1) * 64 * EMB;
            #pragma unroll
            for (int i = 0; i < 4; i++) {
                kreg[i] = ((const float4*)Kn)[i];
                vreg[i] = ((const float4*)Vn)[i];
            }
        }

        // ---- scores S = Qs @ K^T  (m16 x n64 per warp), split 3-MMA
        float s[8][4];
        #pragma unroll
        for (int i = 0; i < 8; i++)
            #pragma unroll
            for (int j = 0; j < 4; j++) s[i][j] = 0.f;
        #pragma unroll
        for (int ks = 0; ks < 4; ks++) {
            uint32_t kbh[4][4], kbl[4][4];
            #pragma unroll
            for (int p = 0; p < 4; p++) {
                ldsm4(kbh[p], smb + OKH + b_off + p * (16 * AT_ROWB) + ks * 32);
                ldsm4(kbl[p], smb + OKL + b_off + p * (16 * AT_ROWB) + ks * 32);
            }
            #pragma unroll
            for (int p = 0; p < 4; p++) {
                #pragma unroll
                for (int half = 0; half < 2; half++) {
                    const uint32_t* bh = &kbh[p][half * 2];
                    const uint32_t* bl = &kbl[p][half * 2];
                    float* sc = s[2 * p + half];
                    mma_bf16(sc, qh[ks], bh);
                    mma_bf16(sc, qh[ks], bl);
                    mma_bf16(sc, ql[ks], bh);
                }
            }
        }

        // ---- online softmax (base-2)
        float rmax0 = -1e30f, rmax1 = -1e30f;
        #pragma unroll
        for (int nt = 0; nt < 8; nt++) {
            rmax0 = fmaxf(rmax0, fmaxf(s[nt][0], s[nt][1]));
            rmax1 = fmaxf(rmax1, fmaxf(s[nt][2], s[nt][3]));
        }
        rmax0 = fmaxf(rmax0, __shfl_xor_sync(0xffffffffu, rmax0, 1));
        rmax0 = fmaxf(rmax0, __shfl_xor_sync(0xffffffffu, rmax0, 2));
        rmax1 = fmaxf(rmax1, __shfl_xor_sync(0xffffffffu, rmax1, 1));
        rmax1 = fmaxf(rmax1, __shfl_xor_sync(0xffffffffu, rmax1, 2));
        float mnew0 = fmaxf(m0, rmax0), mnew1 = fmaxf(m1, rmax1);
        float corr0 = ex2(m0 - mnew0),  corr1 = ex2(m1 - mnew1);
        float rs0 = 0.f, rs1 = 0.f;
        #pragma unroll
        for (int nt = 0; nt < 8; nt++) {
            s[nt][0] = ex2(s[nt][0] - mnew0);
            s[nt][1] = ex2(s[nt][1] - mnew0);
            s[nt][2] = ex2(s[nt][2] - mnew1);
            s[nt][3] = ex2(s[nt][3] - mnew1);
            rs0 += s[nt][0] + s[nt][1];
            rs1 += s[nt][2] + s[nt][3];
        }
        rs0 += __shfl_xor_sync(0xffffffffu, rs0, 1);
        rs0 += __shfl_xor_sync(0xffffffffu, rs0, 2);
        rs1 += __shfl_xor_sync(0xffffffffu, rs1, 1);
        rs1 += __shfl_xor_sync(0xffffffffu, rs1, 2);
        l0 = l0 * corr0 + rs0;
        l1 = l1 * corr1 + rs1;
        m0 = mnew0; m1 = mnew1;
        #pragma unroll
        for (int nt = 0; nt < 8; nt++) {
            oacc[nt][0] *= corr0; oacc[nt][1] *= corr0;
            oacc[nt][2] *= corr1; oacc[nt][3] *= corr1;
        }

        // ---- O += P @ V   (P fragments -> A-fragments in-register)
        #pragma unroll
        for (int ks = 0; ks < 4; ks++) {
            uint32_t pah[4], pal[4];
            split2_u32(s[2 * ks][0],     s[2 * ks][1],     pah[0], pal[0]);
            split2_u32(s[2 * ks][2],     s[2 * ks][3],     pah[1], pal[1]);
            split2_u32(s[2 * ks + 1][0], s[2 * ks + 1][1], pah[2], pal[2]);
            split2_u32(s[2 * ks + 1][2], s[2 * ks + 1][3], pah[3], pal[3]);
            #pragma unroll
            for (int p = 0; p < 4; p++) {
                uint32_t vbh[4], vbl[4];
                ldsm4(vbh, smb + OVH + b_off + p * (16 * AT_ROWB) + ks * 32);
                ldsm4(vbl, smb + OVL + b_off + p * (16 * AT_ROWB) + ks * 32);
                #pragma unroll
                for (int half = 0; half < 2; half++) {
                    const uint32_t* bh = &vbh[half * 2];
                    const uint32_t* bl = &vbl[half * 2];
                    float* oc = oacc[2 * p + half];
                    mma_bf16(oc, pah, bh);
                    mma_bf16(oc, pah, bl);
                    mma_bf16(oc, pal, bh);
                }
            }
        }
        __syncthreads();
    }

    // ---- epilogue: O/l -> bf16 pair
    float inv0 = 1.f / l0, inv1 = 1.f / l1;
    int qrow = q0 + wid * 16 + (lane >> 2);
    size_t t0 = ((size_t)b * SEQ + qrow) * EMB + h * DH;
    size_t t1 = t0 + (size_t)8 * EMB;
    #pragma unroll
    for (int nt = 0; nt < 8; nt++) {
        int d = nt * 8 + (lane & 3) * 2;
        uint32_t hi, lo;
        split2_u32(oacc[nt][0] * inv0, oacc[nt][1] * inv0, hi, lo);
        *(uint32_t*)(Oh + t0 + d) = hi;
        *(uint32_t*)(Ol + t0 + d) = lo;
        split2_u32(oacc[nt][2] * inv1, oacc[nt][3] * inv1, hi, lo);
        *(uint32_t*)(Oh + t1 + d) = hi;
        *(uint32_t*)(Ol + t1 + d) = lo;
    }
}

// ================= launcher =================
extern "C" void kernel_launch(void* const* d_in, const int* in_sizes, int n_in,
                              void* d_out, int out_size) {
    const float* x    = (const float*)d_in[0];
    const float* Wq   = (const float*)d_in[1];
    const float* Wk   = (const float*)d_in[2];
    const float* Wv   = (const float*)d_in[3];
    const float* Wo   = (const float*)d_in[4];
    const float* bo   = (const float*)d_in[5];
    const float* ln1g = (const float*)d_in[6];
    const float* ln1b = (const float*)d_in[7];
    const float* ln2g = (const float*)d_in[8];
    const float* ln2b = (const float*)d_in[9];
    const float* W1   = (const float*)d_in[10];
    const float* b1   = (const float*)d_in[11];
    const float* W2   = (const float*)d_in[12];
    const float* b2   = (const float*)d_in[13];
    float* out = (float*)d_out;

    __nv_bfloat16 *xnh, *xnl, *ath, *atl, *hh, *hl;
    __nv_bfloat16 *wqh, *wql, *wkh, *wkl, *wvh, *wvl, *woh, *wol, *w1h, *w1l, *w2h, *w2l;
    float *q, *k, *v, *x1;
    cudaGetSymbolAddress((void**)&xnh, g_xnh); cudaGetSymbolAddress((void**)&xnl, g_xnl);
    cudaGetSymbolAddress((void**)&ath, g_ath); cudaGetSymbolAddress((void**)&atl, g_atl);
    cudaGetSymbolAddress((void**)&hh,  g_hh);  cudaGetSymbolAddress((void**)&hl,  g_hl);
    cudaGetSymbolAddress((void**)&wqh, g_wqh); cudaGetSymbolAddress((void**)&wql, g_wql);
    cudaGetSymbolAddress((void**)&wkh, g_wkh); cudaGetSymbolAddress((void**)&wkl, g_wkl);
    cudaGetSymbolAddress((void**)&wvh, g_wvh); cudaGetSymbolAddress((void**)&wvl, g_wvl);
    cudaGetSymbolAddress((void**)&woh, g_woh); cudaGetSymbolAddress((void**)&wol, g_wol);
    cudaGetSymbolAddress((void**)&w1h, g_w1h); cudaGetSymbolAddress((void**)&w1l, g_w1l);
    cudaGetSymbolAddress((void**)&w2h, g_w2h); cudaGetSymbolAddress((void**)&w2l, g_w2l);
    cudaGetSymbolAddress((void**)&q,  g_q);  cudaGetSymbolAddress((void**)&k,  g_k);
    cudaGetSymbolAddress((void**)&v,  g_v);  cudaGetSymbolAddress((void**)&x1, g_x1);

    cudaFuncSetAttribute(tc_gemm_kernel<0, false, false, false>,
                         cudaFuncAttributeMaxDynamicSharedMemorySize, GEMM_SMEM);
    cudaFuncSetAttribute(tc_gemm_kernel<0, true, false, true>,
                         cudaFuncAttributeMaxDynamicSharedMemorySize, GEMM_SMEM);
    cudaFuncSetAttribute(tc_gemm_kernel<1, true, true, false>,
                         cudaFuncAttributeMaxDynamicSharedMemorySize, GEMM_SMEM);
    cudaFuncSetAttribute(attention_tc_kernel,
                         cudaFuncAttributeMaxDynamicSharedMemorySize, ATT_SMEM);

    const int CT = 256;
    int nE = EMB * EMB / 4, nF = DFF * EMB / 4;
    cvt_pair_kernel<<<nE / CT, CT>>>(Wq, wqh, wql, nE);
    cvt_pair_kernel<<<nE / CT, CT>>>(Wk, wkh, wkl, nE);
    cvt_pair_kernel<<<nE / CT, CT>>>(Wv, wvh, wvl, nE);
    cvt_pair_kernel<<<nE / CT, CT>>>(Wo, woh, wol, nE);
    cvt_pair_kernel<<<nF / CT, CT>>>(W1, w1h, w1l, nF);
    cvt_pair_kernel<<<nF / CT, CT>>>(W2, w2h, w2l, nF);

    layernorm_kernel<<<T_TOK, 256>>>(x, ln1g, ln1b, xnh, xnl);

    dim3 gE(EMB / 128, T_TOK / 128);
    tc_gemm_kernel<0, false, false, false><<<gE, 256, GEMM_SMEM>>>(
        xnh, xnl, wqh, wql, nullptr, nullptr, q, nullptr, nullptr, T_TOK, EMB, EMB);
    tc_gemm_kernel<0, false, false, false><<<gE, 256, GEMM_SMEM>>>(
        xnh, xnl, wkh, wkl, nullptr, nullptr, k, nullptr, nullptr, T_TOK, EMB, EMB);
    tc_gemm_kernel<0, false, false, false><<<gE, 256, GEMM_SMEM>>>(
        xnh, xnl, wvh, wvl, nullptr, nullptr, v, nullptr, nullptr, T_TOK, EMB, EMB);

    attention_tc_kernel<<<dim3(SEQ / 128, NBATCH * NH), 256, ATT_SMEM>>>(q, k, v, ath, atl);

    tc_gemm_kernel<0, true, false, true><<<gE, 256, GEMM_SMEM>>>(
        ath, atl, woh, wol, bo, x, x1, nullptr, nullptr, T_TOK, EMB, EMB);

    layernorm_kernel<<<T_TOK, 256>>>(x1, ln2g, ln2b, xnh, xnl);

    dim3 gF(DFF / 128, T_TOK / 128);
    tc_gemm_kernel<1, true, true, false><<<gF, 256, GEMM_SMEM>>>(
        xnh, xnl, w1h, w1l, b1, nullptr, nullptr, hh, hl, T_TOK, DFF, EMB);

    tc_gemm_kernel<0, true, false, true><<<gE, 256, GEMM_SMEM>>>(
        hh, hl, w2h, w2l, b2, x1, out, nullptr, nullptr, T_TOK, EMB, DFF);
}

// round 5
// speedup vs baseline: 3.9721x; 1.3146x over previous
#include <cuda_runtime.h>
#include <cuda_bf16.h>
#include <cuda_fp16.h>
#include <math.h>
#include <cstdint>

#define T_TOK 8192
#define EMB   1024
#define DFF   4096
#define NH    16
#define DH    64
#define SEQ   2048
#define NBATCH 4
#define QKVS  3072

// ================= PTX helpers =================
__device__ __forceinline__ uint32_t smem_u32(const void* p) {
    uint32_t a;
    asm("{ .reg .u64 t; cvta.to.shared.u64 t, %1; cvt.u32.u64 %0, t; }" : "=r"(a) : "l"(p));
    return a;
}
#define CP_ASYNC16(dst, src) \
    asm volatile("cp.async.cg.shared.global [%0], [%1], 16;" :: "r"(dst), "l"(src))
#define CP_COMMIT() asm volatile("cp.async.commit_group;" ::: "memory")
#define CP_WAIT1()  asm volatile("cp.async.wait_group 1;" ::: "memory")
#define CP_WAIT0()  asm volatile("cp.async.wait_group 0;" ::: "memory")

__device__ __forceinline__ void ldsm4(uint32_t* r, uint32_t addr) {
    asm volatile("ldmatrix.sync.aligned.m8n8.x4.shared.b16 {%0,%1,%2,%3}, [%4];"
                 : "=r"(r[0]), "=r"(r[1]), "=r"(r[2]), "=r"(r[3]) : "r"(addr));
}
__device__ __forceinline__ void mma_bf16(float* c, const uint32_t* a, const uint32_t* b) {
    asm volatile(
        "mma.sync.aligned.m16n8k16.row.col.f32.bf16.bf16.f32 "
        "{%0,%1,%2,%3}, {%4,%5,%6,%7}, {%8,%9}, {%0,%1,%2,%3};"
        : "+f"(c[0]), "+f"(c[1]), "+f"(c[2]), "+f"(c[3])
        : "r"(a[0]), "r"(a[1]), "r"(a[2]), "r"(a[3]), "r"(b[0]), "r"(b[1]));
}
__device__ __forceinline__ void mma_f16(float* c, const uint32_t* a, const uint32_t* b) {
    asm volatile(
        "mma.sync.aligned.m16n8k16.row.col.f32.f16.f16.f32 "
        "{%0,%1,%2,%3}, {%4,%5,%6,%7}, {%8,%9}, {%0,%1,%2,%3};"
        : "+f"(c[0]), "+f"(c[1]), "+f"(c[2]), "+f"(c[3])
        : "r"(a[0]), "r"(a[1]), "r"(a[2]), "r"(a[3]), "r"(b[0]), "r"(b[1]));
}
__device__ __forceinline__ float ex2(float x) {
    float y;
    asm("ex2.approx.f32 %0, %1;" : "=f"(y) : "f"(x));
    return y;
}

// ================= scratch =================
__device__ __half g_xnh[(size_t)T_TOK * EMB];
__device__ __half g_xnl[(size_t)T_TOK * EMB];
__device__ float g_qkv[(size_t)T_TOK * QKVS];
__device__ float g_x1[(size_t)T_TOK * EMB];
__device__ __half g_ath[(size_t)T_TOK * EMB];
__device__ __half g_atl[(size_t)T_TOK * EMB];
__device__ __half g_hh[(size_t)T_TOK * DFF];
__device__ __half g_hl[(size_t)T_TOK * DFF];
__device__ __half g_wqkv[(size_t)3 * EMB * EMB];
__device__ __half g_wo[(size_t)EMB * EMB];
__device__ __half g_w1[(size_t)DFF * EMB];
__device__ __half g_w2[(size_t)EMB * DFF];

// bf16 split (attention internals)
__device__ __forceinline__ void split_bf16(float x, __nv_bfloat16& h, __nv_bfloat16& l) {
    h = __float2bfloat16(x);
    l = __float2bfloat16(x - __bfloat162float(h));
}
__device__ __forceinline__ void split2_u32(float a, float b, uint32_t& hi, uint32_t& lo) {
    __nv_bfloat16 ha, la, hb, lb;
    split_bf16(a, ha, la); split_bf16(b, hb, lb);
    __nv_bfloat162 h2; h2.x = ha; h2.y = hb;
    __nv_bfloat162 l2; l2.x = la; l2.y = lb;
    hi = *(uint32_t*)&h2; lo = *(uint32_t*)&l2;
}
// fp16 split (GEMM operands)
__device__ __forceinline__ void split_f16(float x, __half& h, __half& l) {
    h = __float2half_rn(x);
    l = __float2half_rn(x - __half2float(h));
}
__device__ __forceinline__ void split2h(float a, float b, uint32_t& hi, uint32_t& lo) {
    __half ha, la, hb, lb;
    split_f16(a, ha, la); split_f16(b, hb, lb);
    __half2 h2 = __halves2half2(ha, hb);
    __half2 l2 = __halves2half2(la, lb);
    hi = *(uint32_t*)&h2; lo = *(uint32_t*)&l2;
}

// ================= weight fp32 -> fp16 =================
__global__ void cvt_h_kernel(const float* __restrict__ w, __half* __restrict__ o, int n4) {
    int i = blockIdx.x * blockDim.x + threadIdx.x;
    if (i >= n4) return;
    float4 v = ((const float4*)w)[i];
    __half2 a = __floats2half2_rn(v.x, v.y);
    __half2 b = __floats2half2_rn(v.z, v.w);
    ((uint32_t*)o)[i * 2 + 0] = *(uint32_t*)&a;
    ((uint32_t*)o)[i * 2 + 1] = *(uint32_t*)&b;
}

// ================= LayerNorm -> fp16 (hi,lo) =================
__global__ void layernorm_kernel(const float* __restrict__ x,
                                 const float* __restrict__ gamma,
                                 const float* __restrict__ beta,
                                 __half* __restrict__ oh, __half* __restrict__ ol) {
    int row = blockIdx.x;
    int t = threadIdx.x;
    const float4* xr = (const float4*)(x + (size_t)row * EMB);
    float4 v = xr[t];
    float s  = v.x + v.y + v.z + v.w;
    float ss = v.x * v.x + v.y * v.y + v.z * v.z + v.w * v.w;
    #pragma unroll
    for (int o = 16; o > 0; o >>= 1) {
        s  += __shfl_xor_sync(0xffffffffu, s,  o);
        ss += __shfl_xor_sync(0xffffffffu, ss, o);
    }
    __shared__ float rs[8], rss[8];
    if ((t & 31) == 0) { rs[t >> 5] = s; rss[t >> 5] = ss; }
    __syncthreads();
    float sum = 0.f, sumsq = 0.f;
    #pragma unroll
    for (int i = 0; i < 8; i++) { sum += rs[i]; sumsq += rss[i]; }
    float mu  = sum * (1.0f / EMB);
    float var = sumsq * (1.0f / EMB) - mu * mu;
    float inv = rsqrtf(var + 1e-5f);
    float4 gg = ((const float4*)gamma)[t];
    float4 bb = ((const float4*)beta)[t];
    float y0 = (v.x - mu) * inv * gg.x + bb.x;
    float y1 = (v.y - mu) * inv * gg.y + bb.y;
    float y2 = (v.z - mu) * inv * gg.z + bb.z;
    float y3 = (v.w - mu) * inv * gg.w + bb.w;
    uint32_t h0, l0, h1, l1;
    split2h(y0, y1, h0, l0);
    split2h(y2, y3, h1, l1);
    size_t base2 = (size_t)row * (EMB / 2) + t * 2;
    ((uint32_t*)oh)[base2 + 0] = h0;
    ((uint32_t*)oh)[base2 + 1] = h1;
    ((uint32_t*)ol)[base2 + 0] = l0;
    ((uint32_t*)ol)[base2 + 1] = l1;
}

// ================= 2-MMA split-fp16 GEMM =================
// C[M,N] = A[M,K] @ B[N,K]^T ; A as (hi,lo) fp16 pair, B plain fp16.
// 128x128 CTA tile, BK=32, 8 warps (2Mx4N), 3-stage cp.async, 1 sync/stage.
#define ROWB      80
#define TILE_B    (128 * ROWB)           // 10240
#define STAGE3_B  (3 * TILE_B)           // 30720
#define GEMM_SMEM (3 * STAGE3_B)         // 92160

template <int OM, bool BIAS, bool RELU, bool RES>
__global__ __launch_bounds__(256)
void tc_gemm_kernel(const __half* __restrict__ Ah, const __half* __restrict__ Al,
                    const __half* __restrict__ B,
                    const float* __restrict__ bias, const float* __restrict__ res,
                    float* __restrict__ Cf,
                    __half* __restrict__ Ch, __half* __restrict__ Cl,
                    int M, int N, int K) {
    extern __shared__ char smc[];
    const uint32_t smb = smem_u32(smc);
    const int tid  = threadIdx.x;
    const int wid  = tid >> 5;
    const int lane = tid & 31;
    const int wm   = wid & 1;
    const int wn   = wid >> 1;
    const int bm   = blockIdx.y * 128;
    const int bn   = blockIdx.x * 128;

    const int r0 = tid >> 2,         c0 = (tid & 3);
    const int r1 = (tid + 256) >> 2, c1 = ((tid + 256) & 3);

    const uint32_t a_off = (uint32_t)((wm * 64 + (lane & 15)) * ROWB + (lane >> 4) * 16);
    const uint32_t b_off = (uint32_t)((wn * 32 + ((lane >> 4) & 1) * 8 + (lane & 7)) * ROWB
                                      + ((lane >> 3) & 1) * 16);

    float acc[4][4][4];
    #pragma unroll
    for (int i = 0; i < 4; i++)
        #pragma unroll
        for (int j = 0; j < 4; j++)
            #pragma unroll
            for (int q = 0; q < 4; q++) acc[i][j][q] = 0.f;

    const int S = K >> 5;

    auto issue = [&](int s, int buf) {
        int k0 = s << 5;
        uint32_t dstb = smb + buf * STAGE3_B;
        {
            uint32_t d = dstb + r0 * ROWB + c0 * 16;
            size_t ao = (size_t)(bm + r0) * K + k0 + c0 * 8;
            size_t bo = (size_t)(bn + r0) * K + k0 + c0 * 8;
            CP_ASYNC16(d,              Ah + ao);
            CP_ASYNC16(d + TILE_B,     Al + ao);
            CP_ASYNC16(d + 2 * TILE_B, B + bo);
        }
        {
            uint32_t d = dstb + r1 * ROWB + c1 * 16;
            size_t ao = (size_t)(bm + r1) * K + k0 + c1 * 8;
            size_t bo = (size_t)(bn + r1) * K + k0 + c1 * 8;
            CP_ASYNC16(d,              Ah + ao);
            CP_ASYNC16(d + TILE_B,     Al + ao);
            CP_ASYNC16(d + 2 * TILE_B, B + bo);
        }
    };

    issue(0, 0); CP_COMMIT();
    if (S > 1) { issue(1, 1); CP_COMMIT(); }

    for (int s = 0; s < S; s++) {
        if (s + 1 < S) { CP_WAIT1(); } else { CP_WAIT0(); }
        __syncthreads();
        if (s + 2 < S) { issue(s + 2, (s + 2) % 3); CP_COMMIT(); }

        const uint32_t stg = smb + (s % 3) * STAGE3_B;
        const uint32_t aB = stg + a_off;
        const uint32_t bB = stg + 2 * TILE_B + b_off;
        #pragma unroll
        for (int ks = 0; ks < 2; ks++) {
            const uint32_t ko = ks * 32;
            uint32_t ahf[4][4], alf[4][4];
            #pragma unroll
            for (int mt = 0; mt < 4; mt++) {
                ldsm4(ahf[mt], aB + mt * (16 * ROWB) + ko);
                ldsm4(alf[mt], aB + TILE_B + mt * (16 * ROWB) + ko);
            }
            uint32_t bhf[2][4];
            #pragma unroll
            for (int p = 0; p < 2; p++)
                ldsm4(bhf[p], bB + p * (16 * ROWB) + ko);
            #pragma unroll
            for (int mt = 0; mt < 4; mt++) {
                #pragma unroll
                for (int nt = 0; nt < 4; nt++) {
                    const uint32_t* bh = &bhf[nt >> 1][(nt & 1) * 2];
                    mma_f16(acc[mt][nt], ahf[mt], bh);
                    mma_f16(acc[mt][nt], alf[mt], bh);
                }
            }
        }
    }

    const int me = bm + wm * 64 + (lane >> 2);
    const int ne = bn + wn * 32 + (lane & 3) * 2;
    #pragma unroll
    for (int mt = 0; mt < 4; mt++) {
        #pragma unroll
        for (int nt = 0; nt < 4; nt++) {
            #pragma unroll
            for (int half = 0; half < 2; half++) {
                int m = me + mt * 16 + half * 8;
                int n = ne + nt * 8;
                float v0 = acc[mt][nt][half * 2 + 0];
                float v1 = acc[mt][nt][half * 2 + 1];
                if (BIAS) {
                    float2 bb = *(const float2*)(bias + n);
                    v0 += bb.x; v1 += bb.y;
                }
                if (RELU) { v0 = fmaxf(v0, 0.f); v1 = fmaxf(v1, 0.f); }
                if (RES) {
                    float2 rr = *(const float2*)(res + (size_t)m * N + n);
                    v0 += rr.x; v1 += rr.y;
                }
                if (OM == 0) {
                    float2 o; o.x = v0; o.y = v1;
                    *(float2*)(Cf + (size_t)m * N + n) = o;
                } else {
                    uint32_t hi, lo;
                    split2h(v0, v1, hi, lo);
                    *(uint32_t*)(Ch + (size_t)m * N + n) = hi;
                    *(uint32_t*)(Cl + (size_t)m * N + n) = lo;
                }
            }
        }
    }
}

// ================= tensor-core flash attention (split-bf16 internals) ========
// reads packed qkv [T_TOK][3072]: q at col 0, k at 1024, v at 2048.
#define AT_ROWB 144
#define OQH 0
#define OQL 18432
#define OKH 36864
#define OKL 46080
#define OVH 55296
#define OVL 64512
#define ATT_SMEM 73728
#define QSCALE 0.18033688f   /* 0.125 * log2(e) */

__global__ __launch_bounds__(256, 1)
void attention_tc_kernel(const float* __restrict__ QKV,
                         __half* __restrict__ Oh, __half* __restrict__ Ol) {
    extern __shared__ char smc[];
    const uint32_t smb = smem_u32(smc);
    const int tid  = threadIdx.x;
    const int wid  = tid >> 5;
    const int lane = tid & 31;
    const int bh = blockIdx.y;
    const int b = bh >> 4, h = bh & 15;
    const int q0 = blockIdx.x * 128;
    const size_t base = ((size_t)b * SEQ) * QKVS + (size_t)h * DH;

    // ---- load Q tile (128x64 f32), scale, split -> SMEM
    {
        int row = tid >> 1;
        int cf  = (tid & 1) * 32;
        const float4* qp = (const float4*)(QKV + base + (size_t)(q0 + row) * QKVS + cf);
        uint32_t off = row * AT_ROWB + cf * 2;
        #pragma unroll
        for (int i = 0; i < 8; i++) {
            float4 v = qp[i];
            uint32_t h0, l0, h1, l1;
            split2_u32(v.x * QSCALE, v.y * QSCALE, h0, l0);
            split2_u32(v.z * QSCALE, v.w * QSCALE, h1, l1);
            *(uint32_t*)(smc + off + OQH + i * 8)     = h0;
            *(uint32_t*)(smc + off + OQH + i * 8 + 4) = h1;
            *(uint32_t*)(smc + off + OQL + i * 8)     = l0;
            *(uint32_t*)(smc + off + OQL + i * 8 + 4) = l1;
        }
    }
    __syncthreads();

    uint32_t qh[4][4], ql[4][4];
    {
        uint32_t a_off = (uint32_t)((wid * 16 + (lane & 15)) * AT_ROWB + (lane >> 4) * 16);
        #pragma unroll
        for (int ks = 0; ks < 4; ks++) {
            ldsm4(qh[ks], smb + OQH + a_off + ks * 32);
            ldsm4(ql[ks], smb + OQL + a_off + ks * 32);
        }
    }

    float oacc[8][4];
    #pragma unroll
    for (int i = 0; i < 8; i++)
        #pragma unroll
        for (int j = 0; j < 4; j++) oacc[i][j] = 0.f;
    float m0 = -1e30f, m1 = -1e30f, l0 = 0.f, l1 = 0.f;

    const int kvr = tid >> 2;
    const int cd  = (tid & 3) * 16;
    const float* Kp = QKV + base + 1024 + (size_t)kvr * QKVS + cd;
    const float* Vp = QKV + base + 2048 + (size_t)kvr * QKVS + cd;

    float4 kreg[4], vreg[4];
    #pragma unroll
    for (int i = 0; i < 4; i++) {
        kreg[i] = ((const float4*)Kp)[i];
        vreg[i] = ((const float4*)Vp)[i];
    }

    const uint32_t b_off = (uint32_t)((((lane >> 4) & 1) * 8 + (lane & 7)) * AT_ROWB
                                      + ((lane >> 3) & 1) * 16);

    for (int t = 0; t < SEQ / 64; t++) {
        {
            uint32_t kd = kvr * AT_ROWB + cd * 2;
            #pragma unroll
            for (int i = 0; i < 4; i++) {
                uint32_t h0, l0u, h1, l1u;
                split2_u32(kreg[i].x, kreg[i].y, h0, l0u);
                split2_u32(kreg[i].z, kreg[i].w, h1, l1u);
                *(uint32_t*)(smc + kd + OKH + i * 8)     = h0;
                *(uint32_t*)(smc + kd + OKH + i * 8 + 4) = h1;
                *(uint32_t*)(smc + kd + OKL + i * 8)     = l0u;
                *(uint32_t*)(smc + kd + OKL + i * 8 + 4) = l1u;
            }
            __nv_bfloat16* vth = (__nv_bfloat16*)(smc + OVH);
            __nv_bfloat16* vtl = (__nv_bfloat16*)(smc + OVL);
            #pragma unroll
            for (int i = 0; i < 4; i++) {
                float vv[4] = {vreg[i].x, vreg[i].y, vreg[i].z, vreg[i].w};
                #pragma unroll
                for (int j = 0; j < 4; j++) {
                    int d = cd + i * 4 + j;
                    __nv_bfloat16 hb, lb;
                    split_bf16(vv[j], hb, lb);
                    vth[d * 72 + kvr] = hb;
                    vtl[d * 72 + kvr] = lb;
                }
            }
        }
        __syncthreads();

        if (t + 1 < SEQ / 64) {
            const float* Kn = Kp + (size_t)(t + 1) * 64 * QKVS;
            const float* Vn = Vp + (size_t)(t + 1) * 64 * QKVS;
            #pragma unroll
            for (int i = 0; i < 4; i++) {
                kreg[i] = ((const float4*)Kn)[i];
                vreg[i] = ((const float4*)Vn)[i];
            }
        }

        float s[8][4];
        #pragma unroll
        for (int i = 0; i < 8; i++)
            #pragma unroll
            for (int j = 0; j < 4; j++) s[i][j] = 0.f;
        #pragma unroll
        for (int ks = 0; ks < 4; ks++) {
            uint32_t kbh[4][4], kbl[4][4];
            #pragma unroll
            for (int p = 0; p < 4; p++) {
                ldsm4(kbh[p], smb + OKH + b_off + p * (16 * AT_ROWB) + ks * 32);
                ldsm4(kbl[p], smb + OKL + b_off + p * (16 * AT_ROWB) + ks * 32);
            }
            #pragma unroll
            for (int p = 0; p < 4; p++) {
                #pragma unroll
                for (int half = 0; half < 2; half++) {
                    const uint32_t* bhp = &kbh[p][half * 2];
                    const uint32_t* blp = &kbl[p][half * 2];
                    float* sc = s[2 * p + half];
                    mma_bf16(sc, qh[ks], bhp);
                    mma_bf16(sc, qh[ks], blp);
                    mma_bf16(sc, ql[ks], bhp);
                }
            }
        }

        float rmax0 = -1e30f, rmax1 = -1e30f;
        #pragma unroll
        for (int nt = 0; nt < 8; nt++) {
            rmax0 = fmaxf(rmax0, fmaxf(s[nt][0], s[nt][1]));
            rmax1 = fmaxf(rmax1, fmaxf(s[nt][2], s[nt][3]));
        }
        rmax0 = fmaxf(rmax0, __shfl_xor_sync(0xffffffffu, rmax0, 1));
        rmax0 = fmaxf(rmax0, __shfl_xor_sync(0xffffffffu, rmax0, 2));
        rmax1 = fmaxf(rmax1, __shfl_xor_sync(0xffffffffu, rmax1, 1));
        rmax1 = fmaxf(rmax1, __shfl_xor_sync(0xffffffffu, rmax1, 2));
        float mnew0 = fmaxf(m0, rmax0), mnew1 = fmaxf(m1, rmax1);
        float corr0 = ex2(m0 - mnew0),  corr1 = ex2(m1 - mnew1);
        float rs0 = 0.f, rs1 = 0.f;
        #pragma unroll
        for (int nt = 0; nt < 8; nt++) {
            s[nt][0] = ex2(s[nt][0] - mnew0);
            s[nt][1] = ex2(s[nt][1] - mnew0);
            s[nt][2] = ex2(s[nt][2] - mnew1);
            s[nt][3] = ex2(s[nt][3] - mnew1);
            rs0 += s[nt][0] + s[nt][1];
            rs1 += s[nt][2] + s[nt][3];
        }
        rs0 += __shfl_xor_sync(0xffffffffu, rs0, 1);
        rs0 += __shfl_xor_sync(0xffffffffu, rs0, 2);
        rs1 += __shfl_xor_sync(0xffffffffu, rs1, 1);
        rs1 += __shfl_xor_sync(0xffffffffu, rs1, 2);
        l0 = l0 * corr0 + rs0;
        l1 = l1 * corr1 + rs1;
        m0 = mnew0; m1 = mnew1;
        #pragma unroll
        for (int nt = 0; nt < 8; nt++) {
            oacc[nt][0] *= corr0; oacc[nt][1] *= corr0;
            oacc[nt][2] *= corr1; oacc[nt][3] *= corr1;
        }

        #pragma unroll
        for (int ks = 0; ks < 4; ks++) {
            uint32_t pah[4], pal[4];
            split2_u32(s[2 * ks][0],     s[2 * ks][1],     pah[0], pal[0]);
            split2_u32(s[2 * ks][2],     s[2 * ks][3],     pah[1], pal[1]);
            split2_u32(s[2 * ks + 1][0], s[2 * ks + 1][1], pah[2], pal[2]);
            split2_u32(s[2 * ks + 1][2], s[2 * ks + 1][3], pah[3], pal[3]);
            #pragma unroll
            for (int p = 0; p < 4; p++) {
                uint32_t vbh[4], vbl[4];
                ldsm4(vbh, smb + OVH + b_off + p * (16 * AT_ROWB) + ks * 32);
                ldsm4(vbl, smb + OVL + b_off + p * (16 * AT_ROWB) + ks * 32);
                #pragma unroll
                for (int half = 0; half < 2; half++) {
                    const uint32_t* bhp = &vbh[half * 2];
                    const uint32_t* blp = &vbl[half * 2];
                    float* oc = oacc[2 * p + half];
                    mma_bf16(oc, pah, bhp);
                    mma_bf16(oc, pah, blp);
                    mma_bf16(oc, pal, bhp);
                }
            }
        }
        __syncthreads();
    }

    float inv0 = 1.f / l0, inv1 = 1.f / l1;
    int qrow = q0 + wid * 16 + (lane >> 2);
    size_t t0 = ((size_t)b * SEQ + qrow) * EMB + h * DH;
    size_t t1 = t0 + (size_t)8 * EMB;
    #pragma unroll
    for (int nt = 0; nt < 8; nt++) {
        int d = nt * 8 + (lane & 3) * 2;
        uint32_t hi, lo;
        split2h(oacc[nt][0] * inv0, oacc[nt][1] * inv0, hi, lo);
        *(uint32_t*)(Oh + t0 + d) = hi;
        *(uint32_t*)(Ol + t0 + d) = lo;
        split2h(oacc[nt][2] * inv1, oacc[nt][3] * inv1, hi, lo);
        *(uint32_t*)(Oh + t1 + d) = hi;
        *(uint32_t*)(Ol + t1 + d) = lo;
    }
}

// ================= launcher =================
extern "C" void kernel_launch(void* const* d_in, const int* in_sizes, int n_in,
                              void* d_out, int out_size) {
    const float* x    = (const float*)d_in[0];
    const float* Wq   = (const float*)d_in[1];
    const float* Wk   = (const float*)d_in[2];
    const float* Wv   = (const float*)d_in[3];
    const float* Wo   = (const float*)d_in[4];
    const float* bo   = (const float*)d_in[5];
    const float* ln1g = (const float*)d_in[6];
    const float* ln1b = (const float*)d_in[7];
    const float* ln2g = (const float*)d_in[8];
    const float* ln2b = (const float*)d_in[9];
    const float* W1   = (const float*)d_in[10];
    const float* b1   = (const float*)d_in[11];
    const float* W2   = (const float*)d_in[12];
    const float* b2   = (const float*)d_in[13];
    float* out = (float*)d_out;

    __half *xnh, *xnl, *ath, *atl, *hh, *hl, *wqkv, *wo, *w1, *w2;
    float *qkv, *x1;
    cudaGetSymbolAddress((void**)&xnh, g_xnh); cudaGetSymbolAddress((void**)&xnl, g_xnl);
    cudaGetSymbolAddress((void**)&ath, g_ath); cudaGetSymbolAddress((void**)&atl, g_atl);
    cudaGetSymbolAddress((void**)&hh,  g_hh);  cudaGetSymbolAddress((void**)&hl,  g_hl);
    cudaGetSymbolAddress((void**)&wqkv, g_wqkv);
    cudaGetSymbolAddress((void**)&wo,  g_wo);
    cudaGetSymbolAddress((void**)&w1,  g_w1);
    cudaGetSymbolAddress((void**)&w2,  g_w2);
    cudaGetSymbolAddress((void**)&qkv, g_qkv);
    cudaGetSymbolAddress((void**)&x1,  g_x1);

    cudaFuncSetAttribute(tc_gemm_kernel<0, false, false, false>,
                         cudaFuncAttributeMaxDynamicSharedMemorySize, GEMM_SMEM);
    cudaFuncSetAttribute(tc_gemm_kernel<0, true, false, true>,
                         cudaFuncAttributeMaxDynamicSharedMemorySize, GEMM_SMEM);
    cudaFuncSetAttribute(tc_gemm_kernel<1, true, true, false>,
                         cudaFuncAttributeMaxDynamicSharedMemorySize, GEMM_SMEM);
    cudaFuncSetAttribute(attention_tc_kernel,
                         cudaFuncAttributeMaxDynamicSharedMemorySize, ATT_SMEM);

    const int CT = 256;
    const int nE = EMB * EMB / 4, nF = DFF * EMB / 4;
    cvt_h_kernel<<<nE / CT, CT>>>(Wq, wqkv,                 nE);
    cvt_h_kernel<<<nE / CT, CT>>>(Wk, wqkv + (size_t)EMB * EMB,     nE);
    cvt_h_kernel<<<nE / CT, CT>>>(Wv, wqkv + (size_t)2 * EMB * EMB, nE);
    cvt_h_kernel<<<nE / CT, CT>>>(Wo, wo, nE);
    cvt_h_kernel<<<nF / CT, CT>>>(W1, w1, nF);
    cvt_h_kernel<<<nF / CT, CT>>>(W2, w2, nF);

    // 1. LN1 -> xn fp16 pair
    layernorm_kernel<<<T_TOK, 256>>>(x, ln1g, ln1b, xnh, xnl);

    // 2. fused QKV projection -> qkv (f32, N=3072)
    dim3 gQKV(QKVS / 128, T_TOK / 128);
    tc_gemm_kernel<0, false, false, false><<<gQKV, 256, GEMM_SMEM>>>(
        xnh, xnl, wqkv, nullptr, nullptr, qkv, nullptr, nullptr, T_TOK, QKVS, EMB);

    // 3. attention -> at fp16 pair
    attention_tc_kernel<<<dim3(SEQ / 128, NBATCH * NH), 256, ATT_SMEM>>>(qkv, ath, atl);

    // 4. O projection + bias + residual(x) -> x1 (f32)
    dim3 gE(EMB / 128, T_TOK / 128);
    tc_gemm_kernel<0, true, false, true><<<gE, 256, GEMM_SMEM>>>(
        ath, atl, wo, bo, x, x1, nullptr, nullptr, T_TOK, EMB, EMB);

    // 5. LN2 -> xn fp16 pair
    layernorm_kernel<<<T_TOK, 256>>>(x1, ln2g, ln2b, xnh, xnl);

    // 6. FF1 + bias + relu -> h fp16 pair
    dim3 gF(DFF / 128, T_TOK / 128);
    tc_gemm_kernel<1, true, true, false><<<gF, 256, GEMM_SMEM>>>(
        xnh, xnl, w1, b1, nullptr, nullptr, hh, hl, T_TOK, DFF, EMB);

    // 7. FF2 + bias + residual(x1) -> out (f32)
    tc_gemm_kernel<0, true, false, true><<<gE, 256, GEMM_SMEM>>>(
        hh, hl, w2, b2, x1, out, nullptr, nullptr, T_TOK, EMB, DFF);
}

// round 6
// speedup vs baseline: 6.0443x; 1.5217x over previous
#include <cuda_runtime.h>
#include <cuda_bf16.h>
#include <cuda_fp16.h>
#include <math.h>
#include <cstdint>

#define T_TOK 8192
#define EMB   1024
#define DFF   4096
#define NH    16
#define DH    64
#define SEQ   2048
#define NBATCH 4
#define QKVS  3072

// ================= PTX helpers =================
__device__ __forceinline__ uint32_t smem_u32(const void* p) {
    uint32_t a;
    asm("{ .reg .u64 t; cvta.to.shared.u64 t, %1; cvt.u32.u64 %0, t; }" : "=r"(a) : "l"(p));
    return a;
}
#define CP_ASYNC16(dst, src) \
    asm volatile("cp.async.cg.shared.global [%0], [%1], 16;" :: "r"(dst), "l"(src))
#define CP_COMMIT() asm volatile("cp.async.commit_group;" ::: "memory")
#define CP_WAIT1()  asm volatile("cp.async.wait_group 1;" ::: "memory")
#define CP_WAIT0()  asm volatile("cp.async.wait_group 0;" ::: "memory")

__device__ __forceinline__ void ldsm4(uint32_t* r, uint32_t addr) {
    asm volatile("ldmatrix.sync.aligned.m8n8.x4.shared.b16 {%0,%1,%2,%3}, [%4];"
                 : "=r"(r[0]), "=r"(r[1]), "=r"(r[2]), "=r"(r[3]) : "r"(addr));
}
__device__ __forceinline__ void mma_bf16(float* c, const uint32_t* a, const uint32_t* b) {
    asm volatile(
        "mma.sync.aligned.m16n8k16.row.col.f32.bf16.bf16.f32 "
        "{%0,%1,%2,%3}, {%4,%5,%6,%7}, {%8,%9}, {%0,%1,%2,%3};"
        : "+f"(c[0]), "+f"(c[1]), "+f"(c[2]), "+f"(c[3])
        : "r"(a[0]), "r"(a[1]), "r"(a[2]), "r"(a[3]), "r"(b[0]), "r"(b[1]));
}
__device__ __forceinline__ void mma_f16(float* c, const uint32_t* a, const uint32_t* b) {
    asm volatile(
        "mma.sync.aligned.m16n8k16.row.col.f32.f16.f16.f32 "
        "{%0,%1,%2,%3}, {%4,%5,%6,%7}, {%8,%9}, {%0,%1,%2,%3};"
        : "+f"(c[0]), "+f"(c[1]), "+f"(c[2]), "+f"(c[3])
        : "r"(a[0]), "r"(a[1]), "r"(a[2]), "r"(a[3]), "r"(b[0]), "r"(b[1]));
}
__device__ __forceinline__ float ex2(float x) {
    float y;
    asm("ex2.approx.f32 %0, %1;" : "=f"(y) : "f"(x));
    return y;
}

// ================= scratch =================
__device__ __half g_xn[(size_t)T_TOK * EMB];
__device__ float g_qkv[(size_t)T_TOK * QKVS];
__device__ float g_x1[(size_t)T_TOK * EMB];
__device__ __half g_at[(size_t)T_TOK * EMB];
__device__ __half g_h [(size_t)T_TOK * DFF];
__device__ __half g_wqkv[(size_t)3 * EMB * EMB];
__device__ __half g_wo[(size_t)EMB * EMB];
__device__ __half g_w1[(size_t)DFF * EMB];
__device__ __half g_w2[(size_t)EMB * DFF];

// bf16 split (attention internals only)
__device__ __forceinline__ void split_bf16(float x, __nv_bfloat16& h, __nv_bfloat16& l) {
    h = __float2bfloat16(x);
    l = __float2bfloat16(x - __bfloat162float(h));
}
__device__ __forceinline__ void split2_u32(float a, float b, uint32_t& hi, uint32_t& lo) {
    __nv_bfloat16 ha, la, hb, lb;
    split_bf16(a, ha, la); split_bf16(b, hb, lb);
    __nv_bfloat162 h2; h2.x = ha; h2.y = hb;
    __nv_bfloat162 l2; l2.x = la; l2.y = lb;
    hi = *(uint32_t*)&h2; lo = *(uint32_t*)&l2;
}
__device__ __forceinline__ uint32_t pack2h(float a, float b) {
    __half2 h = __floats2half2_rn(a, b);
    return *(uint32_t*)&h;
}

// ================= weight fp32 -> fp16 =================
__global__ void cvt_h_kernel(const float* __restrict__ w, __half* __restrict__ o, int n4) {
    int i = blockIdx.x * blockDim.x + threadIdx.x;
    if (i >= n4) return;
    float4 v = ((const float4*)w)[i];
    ((uint32_t*)o)[i * 2 + 0] = pack2h(v.x, v.y);
    ((uint32_t*)o)[i * 2 + 1] = pack2h(v.z, v.w);
}

// ================= LayerNorm -> fp16 =================
__global__ void layernorm_kernel(const float* __restrict__ x,
                                 const float* __restrict__ gamma,
                                 const float* __restrict__ beta,
                                 __half* __restrict__ o) {
    int row = blockIdx.x;
    int t = threadIdx.x;
    const float4* xr = (const float4*)(x + (size_t)row * EMB);
    float4 v = xr[t];
    float s  = v.x + v.y + v.z + v.w;
    float ss = v.x * v.x + v.y * v.y + v.z * v.z + v.w * v.w;
    #pragma unroll
    for (int off = 16; off > 0; off >>= 1) {
        s  += __shfl_xor_sync(0xffffffffu, s,  off);
        ss += __shfl_xor_sync(0xffffffffu, ss, off);
    }
    __shared__ float rs[8], rss[8];
    if ((t & 31) == 0) { rs[t >> 5] = s; rss[t >> 5] = ss; }
    __syncthreads();
    float sum = 0.f, sumsq = 0.f;
    #pragma unroll
    for (int i = 0; i < 8; i++) { sum += rs[i]; sumsq += rss[i]; }
    float mu  = sum * (1.0f / EMB);
    float var = sumsq * (1.0f / EMB) - mu * mu;
    float inv = rsqrtf(var + 1e-5f);
    float4 gg = ((const float4*)gamma)[t];
    float4 bb = ((const float4*)beta)[t];
    float y0 = (v.x - mu) * inv * gg.x + bb.x;
    float y1 = (v.y - mu) * inv * gg.y + bb.y;
    float y2 = (v.z - mu) * inv * gg.z + bb.z;
    float y3 = (v.w - mu) * inv * gg.w + bb.w;
    size_t base2 = (size_t)row * (EMB / 2) + t * 2;
    ((uint32_t*)o)[base2 + 0] = pack2h(y0, y1);
    ((uint32_t*)o)[base2 + 1] = pack2h(y2, y3);
}

// ================= single-MMA fp16 GEMM =================
// C[M,N] = A[M,K] @ B[N,K]^T ; A,B plain fp16, fp32 accum.
// 128x128 CTA tile, BK=32, 8 warps (2Mx4N), 3-stage cp.async, 1 sync/stage.
#define ROWB      80
#define TILE_B    (128 * ROWB)           // 10240
#define STAGE3_B  (2 * TILE_B)           // 20480
#define GEMM_SMEM (3 * STAGE3_B)         // 61440

template <int OM, bool BIAS, bool RELU, bool RES>   // OM: 0=f32 out, 1=fp16 out
__global__ __launch_bounds__(256)
void tc_gemm_kernel(const __half* __restrict__ A, const __half* __restrict__ B,
                    const float* __restrict__ bias, const float* __restrict__ res,
                    float* __restrict__ Cf, __half* __restrict__ Ch,
                    int M, int N, int K) {
    extern __shared__ char smc[];
    const uint32_t smb = smem_u32(smc);
    const int tid  = threadIdx.x;
    const int wid  = tid >> 5;
    const int lane = tid & 31;
    const int wm   = wid & 1;
    const int wn   = wid >> 1;
    const int bm   = blockIdx.y * 128;
    const int bn   = blockIdx.x * 128;

    const int r0 = tid >> 2,         c0 = (tid & 3);
    const int r1 = (tid + 256) >> 2, c1 = ((tid + 256) & 3);

    const uint32_t a_off = (uint32_t)((wm * 64 + (lane & 15)) * ROWB + (lane >> 4) * 16);
    const uint32_t b_off = (uint32_t)((wn * 32 + ((lane >> 4) & 1) * 8 + (lane & 7)) * ROWB
                                      + ((lane >> 3) & 1) * 16);

    float acc[4][4][4];
    #pragma unroll
    for (int i = 0; i < 4; i++)
        #pragma unroll
        for (int j = 0; j < 4; j++)
            #pragma unroll
            for (int q = 0; q < 4; q++) acc[i][j][q] = 0.f;

    const int S = K >> 5;

    auto issue = [&](int s, int buf) {
        int k0 = s << 5;
        uint32_t dstb = smb + buf * STAGE3_B;
        {
            uint32_t d = dstb + r0 * ROWB + c0 * 16;
            CP_ASYNC16(d,          A + (size_t)(bm + r0) * K + k0 + c0 * 8);
            CP_ASYNC16(d + TILE_B, B + (size_t)(bn + r0) * K + k0 + c0 * 8);
        }
        {
            uint32_t d = dstb + r1 * ROWB + c1 * 16;
            CP_ASYNC16(d,          A + (size_t)(bm + r1) * K + k0 + c1 * 8);
            CP_ASYNC16(d + TILE_B, B + (size_t)(bn + r1) * K + k0 + c1 * 8);
        }
    };

    issue(0, 0); CP_COMMIT();
    if (S > 1) { issue(1, 1); CP_COMMIT(); }

    for (int s = 0; s < S; s++) {
        if (s + 1 < S) { CP_WAIT1(); } else { CP_WAIT0(); }
        __syncthreads();
        if (s + 2 < S) { issue(s + 2, (s + 2) % 3); CP_COMMIT(); }

        const uint32_t stg = smb + (s % 3) * STAGE3_B;
        const uint32_t aB = stg + a_off;
        const uint32_t bB = stg + TILE_B + b_off;
        #pragma unroll
        for (int ks = 0; ks < 2; ks++) {
            const uint32_t ko = ks * 32;
            uint32_t ahf[4][4];
            #pragma unroll
            for (int mt = 0; mt < 4; mt++)
                ldsm4(ahf[mt], aB + mt * (16 * ROWB) + ko);
            uint32_t bhf[2][4];
            #pragma unroll
            for (int p = 0; p < 2; p++)
                ldsm4(bhf[p], bB + p * (16 * ROWB) + ko);
            #pragma unroll
            for (int mt = 0; mt < 4; mt++) {
                #pragma unroll
                for (int nt = 0; nt < 4; nt++) {
                    const uint32_t* bh = &bhf[nt >> 1][(nt & 1) * 2];
                    mma_f16(acc[mt][nt], ahf[mt], bh);
                }
            }
        }
    }

    const int me = bm + wm * 64 + (lane >> 2);
    const int ne = bn + wn * 32 + (lane & 3) * 2;
    #pragma unroll
    for (int mt = 0; mt < 4; mt++) {
        #pragma unroll
        for (int nt = 0; nt < 4; nt++) {
            #pragma unroll
            for (int half = 0; half < 2; half++) {
                int m = me + mt * 16 + half * 8;
                int n = ne + nt * 8;
                float v0 = acc[mt][nt][half * 2 + 0];
                float v1 = acc[mt][nt][half * 2 + 1];
                if (BIAS) {
                    float2 bb = *(const float2*)(bias + n);
                    v0 += bb.x; v1 += bb.y;
                }
                if (RELU) { v0 = fmaxf(v0, 0.f); v1 = fmaxf(v1, 0.f); }
                if (RES) {
                    float2 rr = *(const float2*)(res + (size_t)m * N + n);
                    v0 += rr.x; v1 += rr.y;
                }
                if (OM == 0) {
                    float2 o; o.x = v0; o.y = v1;
                    *(float2*)(Cf + (size_t)m * N + n) = o;
                } else {
                    *(uint32_t*)(Ch + (size_t)m * N + n) = pack2h(v0, v1);
                }
            }
        }
    }
}

// ================= tensor-core flash attention (split-bf16 internals) ========
// reads packed qkv [T_TOK][3072]: q at col 0, k at 1024, v at 2048. fp16 out.
#define AT_ROWB 144
#define OQH 0
#define OQL 18432
#define OKH 36864
#define OKL 46080
#define OVH 55296
#define OVL 64512
#define ATT_SMEM 73728
#define QSCALE 0.18033688f   /* 0.125 * log2(e) */

__global__ __launch_bounds__(256, 1)
void attention_tc_kernel(const float* __restrict__ QKV, __half* __restrict__ O) {
    extern __shared__ char smc[];
    const uint32_t smb = smem_u32(smc);
    const int tid  = threadIdx.x;
    const int wid  = tid >> 5;
    const int lane = tid & 31;
    const int bh = blockIdx.y;
    const int b = bh >> 4, h = bh & 15;
    const int q0 = blockIdx.x * 128;
    const size_t base = ((size_t)b * SEQ) * QKVS + (size_t)h * DH;

    {
        int row = tid >> 1;
        int cf  = (tid & 1) * 32;
        const float4* qp = (const float4*)(QKV + base + (size_t)(q0 + row) * QKVS + cf);
        uint32_t off = row * AT_ROWB + cf * 2;
        #pragma unroll
        for (int i = 0; i < 8; i++) {
            float4 v = qp[i];
            uint32_t h0, l0, h1, l1;
            split2_u32(v.x * QSCALE, v.y * QSCALE, h0, l0);
            split2_u32(v.z * QSCALE, v.w * QSCALE, h1, l1);
            *(uint32_t*)(smc + off + OQH + i * 8)     = h0;
            *(uint32_t*)(smc + off + OQH + i * 8 + 4) = h1;
            *(uint32_t*)(smc + off + OQL + i * 8)     = l0;
            *(uint32_t*)(smc + off + OQL + i * 8 + 4) = l1;
        }
    }
    __syncthreads();

    uint32_t qh[4][4], ql[4][4];
    {
        uint32_t a_off = (uint32_t)((wid * 16 + (lane & 15)) * AT_ROWB + (lane >> 4) * 16);
        #pragma unroll
        for (int ks = 0; ks < 4; ks++) {
            ldsm4(qh[ks], smb + OQH + a_off + ks * 32);
            ldsm4(ql[ks], smb + OQL + a_off + ks * 32);
        }
    }

    float oacc[8][4];
    #pragma unroll
    for (int i = 0; i < 8; i++)
        #pragma unroll
        for (int j = 0; j < 4; j++) oacc[i][j] = 0.f;
    float m0 = -1e30f, m1 = -1e30f, l0 = 0.f, l1 = 0.f;

    const int kvr = tid >> 2;
    const int cd  = (tid & 3) * 16;
    const float* Kp = QKV + base + 1024 + (size_t)kvr * QKVS + cd;
    const float* Vp = QKV + base + 2048 + (size_t)kvr * QKVS + cd;

    float4 kreg[4], vreg[4];
    #pragma unroll
    for (int i = 0; i < 4; i++) {
        kreg[i] = ((const float4*)Kp)[i];
        vreg[i] = ((const float4*)Vp)[i];
    }

    const uint32_t b_off = (uint32_t)((((lane >> 4) & 1) * 8 + (lane & 7)) * AT_ROWB
                                      + ((lane >> 3) & 1) * 16);

    for (int t = 0; t < SEQ / 64; t++) {
        {
            uint32_t kd = kvr * AT_ROWB + cd * 2;
            #pragma unroll
            for (int i = 0; i < 4; i++) {
                uint32_t h0, l0u, h1, l1u;
                split2_u32(kreg[i].x, kreg[i].y, h0, l0u);
                split2_u32(kreg[i].z, kreg[i].w, h1, l1u);
                *(uint32_t*)(smc + kd + OKH + i * 8)     = h0;
                *(uint32_t*)(smc + kd + OKH + i * 8 + 4) = h1;
                *(uint32_t*)(smc + kd + OKL + i * 8)     = l0u;
                *(uint32_t*)(smc + kd + OKL + i * 8 + 4) = l1u;
            }
            __nv_bfloat16* vth = (__nv_bfloat16*)(smc + OVH);
            __nv_bfloat16* vtl = (__nv_bfloat16*)(smc + OVL);
            #pragma unroll
            for (int i = 0; i < 4; i++) {
                float vv[4] = {vreg[i].x, vreg[i].y, vreg[i].z, vreg[i].w};
                #pragma unroll
                for (int j = 0; j < 4; j++) {
                    int d = cd + i * 4 + j;
                    __nv_bfloat16 hb, lb;
                    split_bf16(vv[j], hb, lb);
                    vth[d * 72 + kvr] = hb;
                    vtl[d * 72 + kvr] = lb;
                }
            }
        }
        __syncthreads();

        if (t + 1 < SEQ / 64) {
            const float* Kn = Kp + (size_t)(t + 1) * 64 * QKVS;
            const float* Vn = Vp + (size_t)(t + 1) * 64 * QKVS;
            #pragma unroll
            for (int i = 0; i < 4; i++) {
                kreg[i] = ((const float4*)Kn)[i];
                vreg[i] = ((const float4*)Vn)[i];
            }
        }

        float s[8][4];
        #pragma unroll
        for (int i = 0; i < 8; i++)
            #pragma unroll
            for (int j = 0; j < 4; j++) s[i][j] = 0.f;
        #pragma unroll
        for (int ks = 0; ks < 4; ks++) {
            uint32_t kbh[4][4], kbl[4][4];
            #pragma unroll
            for (int p = 0; p < 4; p++) {
                ldsm4(kbh[p], smb + OKH + b_off + p * (16 * AT_ROWB) + ks * 32);
                ldsm4(kbl[p], smb + OKL + b_off + p * (16 * AT_ROWB) + ks * 32);
            }
            #pragma unroll
            for (int p = 0; p < 4; p++) {
                #pragma unroll
                for (int half = 0; half < 2; half++) {
                    const uint32_t* bhp = &kbh[p][half * 2];
                    const uint32_t* blp = &kbl[p][half * 2];
                    float* sc = s[2 * p + half];
                    mma_bf16(sc, qh[ks], bhp);
                    mma_bf16(sc, qh[ks], blp);
                    mma_bf16(sc, ql[ks], bhp);
                }
            }
        }

        float rmax0 = -1e30f, rmax1 = -1e30f;
        #pragma unroll
        for (int nt = 0; nt < 8; nt++) {
            rmax0 = fmaxf(rmax0, fmaxf(s[nt][0], s[nt][1]));
            rmax1 = fmaxf(rmax1, fmaxf(s[nt][2], s[nt][3]));
        }
        rmax0 = fmaxf(rmax0, __shfl_xor_sync(0xffffffffu, rmax0, 1));
        rmax0 = fmaxf(rmax0, __shfl_xor_sync(0xffffffffu, rmax0, 2));
        rmax1 = fmaxf(rmax1, __shfl_xor_sync(0xffffffffu, rmax1, 1));
        rmax1 = fmaxf(rmax1, __shfl_xor_sync(0xffffffffu, rmax1, 2));
        float mnew0 = fmaxf(m0, rmax0), mnew1 = fmaxf(m1, rmax1);
        float corr0 = ex2(m0 - mnew0),  corr1 = ex2(m1 - mnew1);
        float rs0 = 0.f, rs1 = 0.f;
        #pragma unroll
        for (int nt = 0; nt < 8; nt++) {
            s[nt][0] = ex2(s[nt][0] - mnew0);
            s[nt][1] = ex2(s[nt][1] - mnew0);
            s[nt][2] = ex2(s[nt][2] - mnew1);
            s[nt][3] = ex2(s[nt][3] - mnew1);
            rs0 += s[nt][0] + s[nt][1];
            rs1 += s[nt][2] + s[nt][3];
        }
        rs0 += __shfl_xor_sync(0xffffffffu, rs0, 1);
        rs0 += __shfl_xor_sync(0xffffffffu, rs0, 2);
        rs1 += __shfl_xor_sync(0xffffffffu, rs1, 1);
        rs1 += __shfl_xor_sync(0xffffffffu, rs1, 2);
        l0 = l0 * corr0 + rs0;
        l1 = l1 * corr1 + rs1;
        m0 = mnew0; m1 = mnew1;
        #pragma unroll
        for (int nt = 0; nt < 8; nt++) {
            oacc[nt][0] *= corr0; oacc[nt][1] *= corr0;
            oacc[nt][2] *= corr1; oacc[nt][3] *= corr1;
        }

        #pragma unroll
        for (int ks = 0; ks < 4; ks++) {
            uint32_t pah[4], pal[4];
            split2_u32(s[2 * ks][0],     s[2 * ks][1],     pah[0], pal[0]);
            split2_u32(s[2 * ks][2],     s[2 * ks][3],     pah[1], pal[1]);
            split2_u32(s[2 * ks + 1][0], s[2 * ks + 1][1], pah[2], pal[2]);
            split2_u32(s[2 * ks + 1][2], s[2 * ks + 1][3], pah[3], pal[3]);
            #pragma unroll
            for (int p = 0; p < 4; p++) {
                uint32_t vbh[4], vbl[4];
                ldsm4(vbh, smb + OVH + b_off + p * (16 * AT_ROWB) + ks * 32);
                ldsm4(vbl, smb + OVL + b_off + p * (16 * AT_ROWB) + ks * 32);
                #pragma unroll
                for (int half = 0; half < 2; half++) {
                    const uint32_t* bhp = &vbh[half * 2];
                    const uint32_t* blp = &vbl[half * 2];
                    float* oc = oacc[2 * p + half];
                    mma_bf16(oc, pah, bhp);
                    mma_bf16(oc, pah, blp);
                    mma_bf16(oc, pal, bhp);
                }
            }
        }
        __syncthreads();
    }

    float inv0 = 1.f / l0, inv1 = 1.f / l1;
    int qrow = q0 + wid * 16 + (lane >> 2);
    size_t t0 = ((size_t)b * SEQ + qrow) * EMB + h * DH;
    size_t t1 = t0 + (size_t)8 * EMB;
    #pragma unroll
    for (int nt = 0; nt < 8; nt++) {
        int d = nt * 8 + (lane & 3) * 2;
        *(uint32_t*)(O + t0 + d) = pack2h(oacc[nt][0] * inv0, oacc[nt][1] * inv0);
        *(uint32_t*)(O + t1 + d) = pack2h(oacc[nt][2] * inv1, oacc[nt][3] * inv1);
    }
}

// ================= launcher =================
extern "C" void kernel_launch(void* const* d_in, const int* in_sizes, int n_in,
                              void* d_out, int out_size) {
    const float* x    = (const float*)d_in[0];
    const float* Wq   = (const float*)d_in[1];
    const float* Wk   = (const float*)d_in[2];
    const float* Wv   = (const float*)d_in[3];
    const float* Wo   = (const float*)d_in[4];
    const float* bo   = (const float*)d_in[5];
    const float* ln1g = (const float*)d_in[6];
    const float* ln1b = (const float*)d_in[7];
    const float* ln2g = (const float*)d_in[8];
    const float* ln2b = (const float*)d_in[9];
    const float* W1   = (const float*)d_in[10];
    const float* b1   = (const float*)d_in[11];
    const float* W2   = (const float*)d_in[12];
    const float* b2   = (const float*)d_in[13];
    float* out = (float*)d_out;

    __half *xn, *at, *hbuf, *wqkv, *wo, *w1, *w2;
    float *qkv, *x1;
    cudaGetSymbolAddress((void**)&xn, g_xn);
    cudaGetSymbolAddress((void**)&at, g_at);
    cudaGetSymbolAddress((void**)&hbuf, g_h);
    cudaGetSymbolAddress((void**)&wqkv, g_wqkv);
    cudaGetSymbolAddress((void**)&wo,  g_wo);
    cudaGetSymbolAddress((void**)&w1,  g_w1);
    cudaGetSymbolAddress((void**)&w2,  g_w2);
    cudaGetSymbolAddress((void**)&qkv, g_qkv);
    cudaGetSymbolAddress((void**)&x1,  g_x1);

    cudaFuncSetAttribute(tc_gemm_kernel<0, false, false, false>,
                         cudaFuncAttributeMaxDynamicSharedMemorySize, GEMM_SMEM);
    cudaFuncSetAttribute(tc_gemm_kernel<0, true, false, true>,
                         cudaFuncAttributeMaxDynamicSharedMemorySize, GEMM_SMEM);
    cudaFuncSetAttribute(tc_gemm_kernel<1, true, true, false>,
                         cudaFuncAttributeMaxDynamicSharedMemorySize, GEMM_SMEM);
    cudaFuncSetAttribute(attention_tc_kernel,
                         cudaFuncAttributeMaxDynamicSharedMemorySize, ATT_SMEM);

    const int CT = 256;
    const int nE = EMB * EMB / 4, nF = DFF * EMB / 4;
    cvt_h_kernel<<<nE / CT, CT>>>(Wq, wqkv,                         nE);
    cvt_h_kernel<<<nE / CT, CT>>>(Wk, wqkv + (size_t)EMB * EMB,     nE);
    cvt_h_kernel<<<nE / CT, CT>>>(Wv, wqkv + (size_t)2 * EMB * EMB, nE);
    cvt_h_kernel<<<nE / CT, CT>>>(Wo, wo, nE);
    cvt_h_kernel<<<nF / CT, CT>>>(W1, w1, nF);
    cvt_h_kernel<<<nF / CT, CT>>>(W2, w2, nF);

    // 1. LN1 -> xn fp16
    layernorm_kernel<<<T_TOK, 256>>>(x, ln1g, ln1b, xn);

    // 2. fused QKV projection -> qkv (f32, N=3072)
    dim3 gQKV(QKVS / 128, T_TOK / 128);
    tc_gemm_kernel<0, false, false, false><<<gQKV, 256, GEMM_SMEM>>>(
        xn, wqkv, nullptr, nullptr, qkv, nullptr, T_TOK, QKVS, EMB);

    // 3. attention -> at fp16
    attention_tc_kernel<<<dim3(SEQ / 128, NBATCH * NH), 256, ATT_SMEM>>>(qkv, at);

    // 4. O projection + bias + residual(x) -> x1 (f32)
    dim3 gE(EMB / 128, T_TOK / 128);
    tc_gemm_kernel<0, true, false, true><<<gE, 256, GEMM_SMEM>>>(
        at, wo, bo, x, x1, nullptr, T_TOK, EMB, EMB);

    // 5. LN2 -> xn fp16
    layernorm_kernel<<<T_TOK, 256>>>(x1, ln2g, ln2b, xn);

    // 6. FF1 + bias + relu -> h fp16
    dim3 gF(DFF / 128, T_TOK / 128);
    tc_gemm_kernel<1, true, true, false><<<gF, 256, GEMM_SMEM>>>(
        xn, w1, b1, nullptr, nullptr, hbuf, T_TOK, DFF, EMB);

    // 7. FF2 + bias + residual(x1) -> out (f32)
    tc_gemm_kernel<0, true, false, true><<<gE, 256, GEMM_SMEM>>>(
        hbuf, w2, b2, x1, out, nullptr, T_TOK, EMB, DFF);
}

// round 7
// speedup vs baseline: 8.9706x; 1.4841x over previous
#include <cuda_runtime.h>
#include <cuda_bf16.h>
#include <cuda_fp16.h>
#include <math.h>
#include <cstdint>

#define T_TOK 8192
#define EMB   1024
#define DFF   4096
#define NH    16
#define DH    64
#define SEQ   2048
#define NBATCH 4
#define QKVS  3072

// ================= PTX helpers =================
__device__ __forceinline__ uint32_t smem_u32(const void* p) {
    uint32_t a;
    asm("{ .reg .u64 t; cvta.to.shared.u64 t, %1; cvt.u32.u64 %0, t; }" : "=r"(a) : "l"(p));
    return a;
}
#define CP_ASYNC16(dst, src) \
    asm volatile("cp.async.cg.shared.global [%0], [%1], 16;" :: "r"(dst), "l"(src))
#define CP_COMMIT() asm volatile("cp.async.commit_group;" ::: "memory")
#define CP_WAIT1()  asm volatile("cp.async.wait_group 1;" ::: "memory")
#define CP_WAIT0()  asm volatile("cp.async.wait_group 0;" ::: "memory")

__device__ __forceinline__ void ldsm4(uint32_t* r, uint32_t addr) {
    asm volatile("ldmatrix.sync.aligned.m8n8.x4.shared.b16 {%0,%1,%2,%3}, [%4];"
                 : "=r"(r[0]), "=r"(r[1]), "=r"(r[2]), "=r"(r[3]) : "r"(addr));
}
__device__ __forceinline__ void ldsm4t(uint32_t* r, uint32_t addr) {
    asm volatile("ldmatrix.sync.aligned.m8n8.x4.trans.shared.b16 {%0,%1,%2,%3}, [%4];"
                 : "=r"(r[0]), "=r"(r[1]), "=r"(r[2]), "=r"(r[3]) : "r"(addr));
}
__device__ __forceinline__ void mma_f16(float* c, const uint32_t* a, const uint32_t* b) {
    asm volatile(
        "mma.sync.aligned.m16n8k16.row.col.f32.f16.f16.f32 "
        "{%0,%1,%2,%3}, {%4,%5,%6,%7}, {%8,%9}, {%0,%1,%2,%3};"
        : "+f"(c[0]), "+f"(c[1]), "+f"(c[2]), "+f"(c[3])
        : "r"(a[0]), "r"(a[1]), "r"(a[2]), "r"(a[3]), "r"(b[0]), "r"(b[1]));
}
__device__ __forceinline__ float ex2(float x) {
    float y;
    asm("ex2.approx.f32 %0, %1;" : "=f"(y) : "f"(x));
    return y;
}
__device__ __forceinline__ uint32_t pack2h(float a, float b) {
    __half2 h = __floats2half2_rn(a, b);
    return *(uint32_t*)&h;
}

// ================= scratch =================
__device__ __half g_xn[(size_t)T_TOK * EMB];
__device__ __half g_qkvh[(size_t)T_TOK * QKVS];
__device__ float g_x1[(size_t)T_TOK * EMB];
__device__ __half g_at[(size_t)T_TOK * EMB];
__device__ __half g_h [(size_t)T_TOK * DFF];
__device__ __half g_wqkv[(size_t)3 * EMB * EMB];
__device__ __half g_wo[(size_t)EMB * EMB];
__device__ __half g_w1[(size_t)DFF * EMB];
__device__ __half g_w2[(size_t)EMB * DFF];

// ================= weight fp32 -> fp16 (optional scale) =================
__global__ void cvt_h_kernel(const float* __restrict__ w, __half* __restrict__ o,
                             int n4, float scale) {
    int i = blockIdx.x * blockDim.x + threadIdx.x;
    if (i >= n4) return;
    float4 v = ((const float4*)w)[i];
    ((uint32_t*)o)[i * 2 + 0] = pack2h(v.x * scale, v.y * scale);
    ((uint32_t*)o)[i * 2 + 1] = pack2h(v.z * scale, v.w * scale);
}

// ================= LayerNorm -> fp16 =================
__global__ void layernorm_kernel(const float* __restrict__ x,
                                 const float* __restrict__ gamma,
                                 const float* __restrict__ beta,
                                 __half* __restrict__ o) {
    int row = blockIdx.x;
    int t = threadIdx.x;
    const float4* xr = (const float4*)(x + (size_t)row * EMB);
    float4 v = xr[t];
    float s  = v.x + v.y + v.z + v.w;
    float ss = v.x * v.x + v.y * v.y + v.z * v.z + v.w * v.w;
    #pragma unroll
    for (int off = 16; off > 0; off >>= 1) {
        s  += __shfl_xor_sync(0xffffffffu, s,  off);
        ss += __shfl_xor_sync(0xffffffffu, ss, off);
    }
    __shared__ float rs[8], rss[8];
    if ((t & 31) == 0) { rs[t >> 5] = s; rss[t >> 5] = ss; }
    __syncthreads();
    float sum = 0.f, sumsq = 0.f;
    #pragma unroll
    for (int i = 0; i < 8; i++) { sum += rs[i]; sumsq += rss[i]; }
    float mu  = sum * (1.0f / EMB);
    float var = sumsq * (1.0f / EMB) - mu * mu;
    float inv = rsqrtf(var + 1e-5f);
    float4 gg = ((const float4*)gamma)[t];
    float4 bb = ((const float4*)beta)[t];
    float y0 = (v.x - mu) * inv * gg.x + bb.x;
    float y1 = (v.y - mu) * inv * gg.y + bb.y;
    float y2 = (v.z - mu) * inv * gg.z + bb.z;
    float y3 = (v.w - mu) * inv * gg.w + bb.w;
    size_t base2 = (size_t)row * (EMB / 2) + t * 2;
    ((uint32_t*)o)[base2 + 0] = pack2h(y0, y1);
    ((uint32_t*)o)[base2 + 1] = pack2h(y2, y3);
}

// ================= single-MMA fp16 GEMM (validated R6) =================
#define ROWB      80
#define TILE_B    (128 * ROWB)
#define STAGE3_B  (2 * TILE_B)
#define GEMM_SMEM (3 * STAGE3_B)

template <int OM, bool BIAS, bool RELU, bool RES>   // OM: 0=f32 out, 1=fp16 out
__global__ __launch_bounds__(256)
void tc_gemm_kernel(const __half* __restrict__ A, const __half* __restrict__ B,
                    const float* __restrict__ bias, const float* __restrict__ res,
                    float* __restrict__ Cf, __half* __restrict__ Ch,
                    int M, int N, int K) {
    extern __shared__ char smc[];
    const uint32_t smb = smem_u32(smc);
    const int tid  = threadIdx.x;
    const int wid  = tid >> 5;
    const int lane = tid & 31;
    const int wm   = wid & 1;
    const int wn   = wid >> 1;
    const int bm   = blockIdx.y * 128;
    const int bn   = blockIdx.x * 128;

    const int r0 = tid >> 2,         c0 = (tid & 3);
    const int r1 = (tid + 256) >> 2, c1 = ((tid + 256) & 3);

    const uint32_t a_off = (uint32_t)((wm * 64 + (lane & 15)) * ROWB + (lane >> 4) * 16);
    const uint32_t b_off = (uint32_t)((wn * 32 + ((lane >> 4) & 1) * 8 + (lane & 7)) * ROWB
                                      + ((lane >> 3) & 1) * 16);

    float acc[4][4][4];
    #pragma unroll
    for (int i = 0; i < 4; i++)
        #pragma unroll
        for (int j = 0; j < 4; j++)
            #pragma unroll
            for (int q = 0; q < 4; q++) acc[i][j][q] = 0.f;

    const int S = K >> 5;

    auto issue = [&](int s, int buf) {
        int k0 = s << 5;
        uint32_t dstb = smb + buf * STAGE3_B;
        {
            uint32_t d = dstb + r0 * ROWB + c0 * 16;
            CP_ASYNC16(d,          A + (size_t)(bm + r0) * K + k0 + c0 * 8);
            CP_ASYNC16(d + TILE_B, B + (size_t)(bn + r0) * K + k0 + c0 * 8);
        }
        {
            uint32_t d = dstb + r1 * ROWB + c1 * 16;
            CP_ASYNC16(d,          A + (size_t)(bm + r1) * K + k0 + c1 * 8);
            CP_ASYNC16(d + TILE_B, B + (size_t)(bn + r1) * K + k0 + c1 * 8);
        }
    };

    issue(0, 0); CP_COMMIT();
    if (S > 1) { issue(1, 1); CP_COMMIT(); }

    for (int s = 0; s < S; s++) {
        if (s + 1 < S) { CP_WAIT1(); } else { CP_WAIT0(); }
        __syncthreads();
        if (s + 2 < S) { issue(s + 2, (s + 2) % 3); CP_COMMIT(); }

        const uint32_t stg = smb + (s % 3) * STAGE3_B;
        const uint32_t aB = stg + a_off;
        const uint32_t bB = stg + TILE_B + b_off;
        #pragma unroll
        for (int ks = 0; ks < 2; ks++) {
            const uint32_t ko = ks * 32;
            uint32_t ahf[4][4];
            #pragma unroll
            for (int mt = 0; mt < 4; mt++)
                ldsm4(ahf[mt], aB + mt * (16 * ROWB) + ko);
            uint32_t bhf[2][4];
            #pragma unroll
            for (int p = 0; p < 2; p++)
                ldsm4(bhf[p], bB + p * (16 * ROWB) + ko);
            #pragma unroll
            for (int mt = 0; mt < 4; mt++) {
                #pragma unroll
                for (int nt = 0; nt < 4; nt++) {
                    const uint32_t* bh = &bhf[nt >> 1][(nt & 1) * 2];
                    mma_f16(acc[mt][nt], ahf[mt], bh);
                }
            }
        }
    }

    const int me = bm + wm * 64 + (lane >> 2);
    const int ne = bn + wn * 32 + (lane & 3) * 2;
    #pragma unroll
    for (int mt = 0; mt < 4; mt++) {
        #pragma unroll
        for (int nt = 0; nt < 4; nt++) {
            #pragma unroll
            for (int half = 0; half < 2; half++) {
                int m = me + mt * 16 + half * 8;
                int n = ne + nt * 8;
                float v0 = acc[mt][nt][half * 2 + 0];
                float v1 = acc[mt][nt][half * 2 + 1];
                if (BIAS) {
                    float2 bb = *(const float2*)(bias + n);
                    v0 += bb.x; v1 += bb.y;
                }
                if (RELU) { v0 = fmaxf(v0, 0.f); v1 = fmaxf(v1, 0.f); }
                if (RES) {
                    float2 rr = *(const float2*)(res + (size_t)m * N + n);
                    v0 += rr.x; v1 += rr.y;
                }
                if (OM == 0) {
                    float2 o; o.x = v0; o.y = v1;
                    *(float2*)(Cf + (size_t)m * N + n) = o;
                } else {
                    *(uint32_t*)(Ch + (size_t)m * N + n) = pack2h(v0, v1);
                }
            }
        }
    }
}

// ================= fp16 flash attention (single-MMA, cp.async K/V) ==========
// qkv fp16 [T_TOK][3072]: q (pre-scaled by 0.125*log2e) at 0, k at 1024, v at 2048.
// grid (SEQ/128, NB*NH), 256 thr (8 warps x m16). kv tile 64, double-buffered.
#define AROWB 144                      /* 64 halves + 16B pad */
#define AQ_B  (128 * AROWB)            /* 18432 */
#define AKV_B (64 * AROWB)             /* 9216  */
#define OKV(buf) (AQ_B + (buf) * 2 * AKV_B)
#define ATT_SMEM (AQ_B + 4 * AKV_B)    /* 55296 */
#define NKV (SEQ / 64)

__global__ __launch_bounds__(256, 1)
void attention_tc_kernel(const __half* __restrict__ QKV, __half* __restrict__ O) {
    extern __shared__ char smc[];
    const uint32_t smb = smem_u32(smc);
    const int tid  = threadIdx.x;
    const int wid  = tid >> 5;
    const int lane = tid & 31;
    const int bh = blockIdx.y;
    const int b = bh >> 4, h = bh & 15;
    const int q0 = blockIdx.x * 128;
    const size_t base = ((size_t)b * SEQ) * QKVS + (size_t)h * DH;

    const __half* Kg = QKV + base + 1024;
    const __half* Vg = QKV + base + 2048;

    auto issue_kv = [&](int t, int buf) {
        const __half* Kt = Kg + (size_t)(t * 64) * QKVS;
        const __half* Vt = Vg + (size_t)(t * 64) * QKVS;
        #pragma unroll
        for (int i = 0; i < 2; i++) {
            int id = tid + i * 256;
            int r = id >> 3, c = id & 7;
            uint32_t d = smb + OKV(buf) + r * AROWB + c * 16;
            CP_ASYNC16(d,         Kt + (size_t)r * QKVS + c * 8);
            CP_ASYNC16(d + AKV_B, Vt + (size_t)r * QKVS + c * 8);
        }
    };

    // Q tile (128x64 fp16) + kv(0) in group 0; kv(1) in group 1
    {
        const __half* Qt = QKV + base + (size_t)q0 * QKVS;
        #pragma unroll
        for (int i = 0; i < 4; i++) {
            int id = tid + i * 256;
            int r = id >> 3, c = id & 7;
            CP_ASYNC16(smb + r * AROWB + c * 16, Qt + (size_t)r * QKVS + c * 8);
        }
        issue_kv(0, 0); CP_COMMIT();
        issue_kv(1, 1); CP_COMMIT();
    }
    CP_WAIT1();
    __syncthreads();

    // per-warp Q A-fragments
    uint32_t qf[4][4];
    {
        uint32_t a_off = (uint32_t)((wid * 16 + (lane & 15)) * AROWB + (lane >> 4) * 16);
        #pragma unroll
        for (int ks = 0; ks < 4; ks++)
            ldsm4(qf[ks], smb + a_off + ks * 32);
    }

    // K B-fragment lane offset (non-trans, n=kv rows)
    const uint32_t kb_off = (uint32_t)(( ((lane >> 4) & 1) * 8 + (lane & 7) ) * AROWB
                                       + ((lane >> 3) & 1) * 16);
    // V B-fragment lane offset (trans: rows = kv, cols = d)
    const uint32_t vb_off = (uint32_t)(( ((lane >> 3) & 1) * 8 + (lane & 7) ) * AROWB
                                       + ((lane >> 4) & 1) * 16);

    float oacc[8][4];
    #pragma unroll
    for (int i = 0; i < 8; i++)
        #pragma unroll
        for (int j = 0; j < 4; j++) oacc[i][j] = 0.f;
    float m0 = -1e30f, m1 = -1e30f, l0 = 0.f, l1 = 0.f;

    for (int t = 0; t < NKV; t++) {
        const int buf = t & 1;
        const uint32_t kB = smb + OKV(buf) + kb_off;
        const uint32_t vB = smb + OKV(buf) + AKV_B + vb_off;

        // ---- scores S = Qs @ K^T (m16 x n64 per warp)
        float s[8][4];
        #pragma unroll
        for (int i = 0; i < 8; i++)
            #pragma unroll
            for (int j = 0; j < 4; j++) s[i][j] = 0.f;
        #pragma unroll
        for (int ks = 0; ks < 4; ks++) {
            uint32_t kb[4][4];
            #pragma unroll
            for (int p = 0; p < 4; p++)
                ldsm4(kb[p], kB + p * (16 * AROWB) + ks * 32);
            #pragma unroll
            for (int p = 0; p < 4; p++) {
                #pragma unroll
                for (int half = 0; half < 2; half++)
                    mma_f16(s[2 * p + half], qf[ks], &kb[p][half * 2]);
            }
        }

        // ---- online softmax (base-2; Q pre-scaled by log2e)
        float rmax0 = -1e30f, rmax1 = -1e30f;
        #pragma unroll
        for (int nt = 0; nt < 8; nt++) {
            rmax0 = fmaxf(rmax0, fmaxf(s[nt][0], s[nt][1]));
            rmax1 = fmaxf(rmax1, fmaxf(s[nt][2], s[nt][3]));
        }
        rmax0 = fmaxf(rmax0, __shfl_xor_sync(0xffffffffu, rmax0, 1));
        rmax0 = fmaxf(rmax0, __shfl_xor_sync(0xffffffffu, rmax0, 2));
        rmax1 = fmaxf(rmax1, __shfl_xor_sync(0xffffffffu, rmax1, 1));
        rmax1 = fmaxf(rmax1, __shfl_xor_sync(0xffffffffu, rmax1, 2));
        float mnew0 = fmaxf(m0, rmax0), mnew1 = fmaxf(m1, rmax1);
        float corr0 = ex2(m0 - mnew0),  corr1 = ex2(m1 - mnew1);
        float rs0 = 0.f, rs1 = 0.f;
        #pragma unroll
        for (int nt = 0; nt < 8; nt++) {
            s[nt][0] = ex2(s[nt][0] - mnew0);
            s[nt][1] = ex2(s[nt][1] - mnew0);
            s[nt][2] = ex2(s[nt][2] - mnew1);
            s[nt][3] = ex2(s[nt][3] - mnew1);
            rs0 += s[nt][0] + s[nt][1];
            rs1 += s[nt][2] + s[nt][3];
        }
        rs0 += __shfl_xor_sync(0xffffffffu, rs0, 1);
        rs0 += __shfl_xor_sync(0xffffffffu, rs0, 2);
        rs1 += __shfl_xor_sync(0xffffffffu, rs1, 1);
        rs1 += __shfl_xor_sync(0xffffffffu, rs1, 2);
        l0 = l0 * corr0 + rs0;
        l1 = l1 * corr1 + rs1;
        m0 = mnew0; m1 = mnew1;
        #pragma unroll
        for (int nt = 0; nt < 8; nt++) {
            oacc[nt][0] *= corr0; oacc[nt][1] *= corr0;
            oacc[nt][2] *= corr1; oacc[nt][3] *= corr1;
        }

        // ---- O += P @ V (P fp16 A-frags; V via ldmatrix.trans on [kv][d])
        #pragma unroll
        for (int ks = 0; ks < 4; ks++) {
            uint32_t pa[4];
            pa[0] = pack2h(s[2 * ks][0],     s[2 * ks][1]);
            pa[1] = pack2h(s[2 * ks][2],     s[2 * ks][3]);
            pa[2] = pack2h(s[2 * ks + 1][0], s[2 * ks + 1][1]);
            pa[3] = pack2h(s[2 * ks + 1][2], s[2 * ks + 1][3]);
            #pragma unroll
            for (int p = 0; p < 4; p++) {
                uint32_t vb[4];
                ldsm4t(vb, vB + ks * (16 * AROWB) + p * 32);
                #pragma unroll
                for (int half = 0; half < 2; half++)
                    mma_f16(oacc[2 * p + half], pa, &vb[half * 2]);
            }
        }
        __syncthreads();

        // ---- prefetch kv(t+2) into this buffer; ensure kv(t+1) landed
        if (t + 2 < NKV) {
            issue_kv(t + 2, buf); CP_COMMIT();
            CP_WAIT1();
        } else if (t + 1 < NKV) {
            CP_WAIT0();
        }
        __syncthreads();
    }

    // ---- epilogue: O/l -> fp16
    float inv0 = 1.f / l0, inv1 = 1.f / l1;
    int qrow = q0 + wid * 16 + (lane >> 2);
    size_t t0 = ((size_t)b * SEQ + qrow) * EMB + h * DH;
    size_t t1 = t0 + (size_t)8 * EMB;
    #pragma unroll
    for (int nt = 0; nt < 8; nt++) {
        int d = nt * 8 + (lane & 3) * 2;
        *(uint32_t*)(O + t0 + d) = pack2h(oacc[nt][0] * inv0, oacc[nt][1] * inv0);
        *(uint32_t*)(O + t1 + d) = pack2h(oacc[nt][2] * inv1, oacc[nt][3] * inv1);
    }
}

// ================= launcher =================
extern "C" void kernel_launch(void* const* d_in, const int* in_sizes, int n_in,
                              void* d_out, int out_size) {
    const float* x    = (const float*)d_in[0];
    const float* Wq   = (const float*)d_in[1];
    const float* Wk   = (const float*)d_in[2];
    const float* Wv   = (const float*)d_in[3];
    const float* Wo   = (const float*)d_in[4];
    const float* bo   = (const float*)d_in[5];
    const float* ln1g = (const float*)d_in[6];
    const float* ln1b = (const float*)d_in[7];
    const float* ln2g = (const float*)d_in[8];
    const float* ln2b = (const float*)d_in[9];
    const float* W1   = (const float*)d_in[10];
    const float* b1   = (const float*)d_in[11];
    const float* W2   = (const float*)d_in[12];
    const float* b2   = (const float*)d_in[13];
    float* out = (float*)d_out;

    __half *xn, *at, *hbuf, *wqkv, *wo, *w1, *w2, *qkvh;
    float *x1;
    cudaGetSymbolAddress((void**)&xn, g_xn);
    cudaGetSymbolAddress((void**)&at, g_at);
    cudaGetSymbolAddress((void**)&hbuf, g_h);
    cudaGetSymbolAddress((void**)&wqkv, g_wqkv);
    cudaGetSymbolAddress((void**)&wo,  g_wo);
    cudaGetSymbolAddress((void**)&w1,  g_w1);
    cudaGetSymbolAddress((void**)&w2,  g_w2);
    cudaGetSymbolAddress((void**)&qkvh, g_qkvh);
    cudaGetSymbolAddress((void**)&x1,  g_x1);

    cudaFuncSetAttribute(tc_gemm_kernel<1, false, false, false>,
                         cudaFuncAttributeMaxDynamicSharedMemorySize, GEMM_SMEM);
    cudaFuncSetAttribute(tc_gemm_kernel<0, true, false, true>,
                         cudaFuncAttributeMaxDynamicSharedMemorySize, GEMM_SMEM);
    cudaFuncSetAttribute(tc_gemm_kernel<1, true, true, false>,
                         cudaFuncAttributeMaxDynamicSharedMemorySize, GEMM_SMEM);
    cudaFuncSetAttribute(attention_tc_kernel,
                         cudaFuncAttributeMaxDynamicSharedMemorySize, ATT_SMEM);

    const float QS = 0.1803368801111204f;  // 0.125 * log2(e)
    const int CT = 256;
    const int nE = EMB * EMB / 4, nF = DFF * EMB / 4;
    cvt_h_kernel<<<nE / CT, CT>>>(Wq, wqkv,                         nE, QS);
    cvt_h_kernel<<<nE / CT, CT>>>(Wk, wqkv + (size_t)EMB * EMB,     nE, 1.f);
    cvt_h_kernel<<<nE / CT, CT>>>(Wv, wqkv + (size_t)2 * EMB * EMB, nE, 1.f);
    cvt_h_kernel<<<nE / CT, CT>>>(Wo, wo, nE, 1.f);
    cvt_h_kernel<<<nF / CT, CT>>>(W1, w1, nF, 1.f);
    cvt_h_kernel<<<nF / CT, CT>>>(W2, w2, nF, 1.f);

    // 1. LN1 -> xn fp16
    layernorm_kernel<<<T_TOK, 256>>>(x, ln1g, ln1b, xn);

    // 2. fused QKV projection -> qkv fp16 (Q pre-scaled via weights)
    dim3 gQKV(QKVS / 128, T_TOK / 128);
    tc_gemm_kernel<1, false, false, false><<<gQKV, 256, GEMM_SMEM>>>(
        xn, wqkv, nullptr, nullptr, nullptr, qkvh, T_TOK, QKVS, EMB);

    // 3. attention -> at fp16
    attention_tc_kernel<<<dim3(SEQ / 128, NBATCH * NH), 256, ATT_SMEM>>>(qkvh, at);

    // 4. O projection + bias + residual(x) -> x1 (f32)
    dim3 gE(EMB / 128, T_TOK / 128);
    tc_gemm_kernel<0, true, false, true><<<gE, 256, GEMM_SMEM>>>(
        at, wo, bo, x, x1, nullptr, T_TOK, EMB, EMB);

    // 5. LN2 -> xn fp16
    layernorm_kernel<<<T_TOK, 256>>>(x1, ln2g, ln2b, xn);

    // 6. FF1 + bias + relu -> h fp16
    dim3 gF(DFF / 128, T_TOK / 128);
    tc_gemm_kernel<1, true, true, false><<<gF, 256, GEMM_SMEM>>>(
        xn, w1, b1, nullptr, nullptr, hbuf, T_TOK, DFF, EMB);

    // 7. FF2 + bias + residual(x1) -> out (f32)
    tc_gemm_kernel<0, true, false, true><<<gE, 256, GEMM_SMEM>>>(
        hbuf, w2, b2, x1, out, nullptr, T_TOK, EMB, DFF);
}